// round 11
// baseline (speedup 1.0000x reference)
#include <cuda_runtime.h>
#include <math.h>

#define NB   2048
#define NTHR 1024

// ---------------- global scratch -------------------------------------------
__device__ float2 g_psi[NB * 4 * 10];       // encoded per-wire vectors
__device__ float2 g_Elay[8 * 100];          // merged layer 10x10 complex gates (D@S)
__device__ __align__(16) float2 g_Xm[2][10000];   // scaled generators (CX, BS)
__device__ __align__(16) float2 g_Tp[2][2][10000];// Taylor term ping-pong
__device__ __align__(16) float2 g_Sp[2][2][10000];// partial sum ping-pong
__device__ __align__(16) float2 g_CX2[10000];     // CX duplicated pairs [kk][o][ll] = (u,u)
__device__ __align__(16) float4 g_BS4[670];       // BS blocks packed (x,x,-y,y)
__device__ __align__(16) float4 g_E4[800];        // E gates packed (x,x,-y,y)

// BS block tables
__constant__ int d_bsz[19] = {1,2,3,4,5,6,7,8,9,10,9,8,7,6,5,4,3,2,1};
__constant__ int d_off[19] = {0,1,5,14,30,55,91,140,204,285,385,466,530,579,615,640,656,665,669};
__constant__ int d_lo[19]  = {0,0,0,0,0,0,0,0,0,0,1,2,3,4,5,6,7,8,9};

// ---------------- helpers ---------------------------------------------------
__device__ __forceinline__ float2 cmul(float2 a, float2 b) {
    return make_float2(a.x * b.x - a.y * b.y, a.x * b.y + a.y * b.x);
}
__device__ __forceinline__ void cmacc(float2& acc, float2 a, float2 b) {
    acc.x = fmaf(a.x, b.x, fmaf(-a.y, b.y, acc.x));
    acc.y = fmaf(a.x, b.y, fmaf( a.y, b.x, acc.y));
}
// packed f32x2 fma: d = a*b + d (elementwise on the two f32 lanes)
__device__ __forceinline__ void fma2(unsigned long long& d, unsigned long long a, unsigned long long b) {
    asm("fma.rn.f32x2 %0, %1, %2, %0;" : "+l"(d) : "l"(a), "l"(b));
}
// swap the two f32 lanes of a packed value
__device__ __forceinline__ unsigned long long swap2(unsigned long long v) {
    unsigned long long r;
    asm("{\n\t.reg .b32 lo, hi;\n\tmov.b64 {lo, hi}, %1;\n\tmov.b64 %0, {hi, lo};\n\t}"
        : "=l"(r) : "l"(v));
    return r;
}

// ---------------- 10x10 expm (block-cooperative, >=128 thr) -----------------
__device__ void expm10(float2* X, float2* S, float2* T, float2* T2, float* red, int t) {
    if (t < 10) {
        float s = 0.f;
        for (int j = 0; j < 10; j++) { float2 v = X[t * 10 + j]; s += fabsf(v.x) + fabsf(v.y); }
        red[t] = s;
    }
    __syncthreads();
    if (t == 0) {
        float m = 0.f;
        for (int i = 0; i < 10; i++) m = fmaxf(m, red[i]);
        int s = 0;
        while (m > 0.5f && s < 40) { m *= 0.5f; s++; }
        red[10] = (float)s;
    }
    __syncthreads();
    int s = (int)red[10];
    float sc = ldexpf(1.f, -s);
    if (t < 100) {
        X[t].x *= sc; X[t].y *= sc;
        T[t] = X[t];
        float2 v = X[t];
        if (t % 11 == 0) v.x += 1.f;
        S[t] = v;
    }
    __syncthreads();
    for (int j = 2; j <= 13; j++) {
        float inv = 1.f / (float)j;
        if (t < 100) {
            int i = t / 10, c = t % 10;
            float2 acc = make_float2(0.f, 0.f);
#pragma unroll
            for (int k = 0; k < 10; k++) cmacc(acc, T[i * 10 + k], X[k * 10 + c]);
            T2[t] = make_float2(acc.x * inv, acc.y * inv);
        }
        __syncthreads();
        if (t < 100) { T[t] = T2[t]; S[t].x += T2[t].x; S[t].y += T2[t].y; }
        __syncthreads();
    }
    for (int it = 0; it < s; it++) {
        if (t < 100) {
            int i = t / 10, c = t % 10;
            float2 acc = make_float2(0.f, 0.f);
#pragma unroll
            for (int k = 0; k < 10; k++) cmacc(acc, S[i * 10 + k], S[k * 10 + c]);
            T2[t] = acc;
        }
        __syncthreads();
        if (t < 100) S[t] = T2[t];
        __syncthreads();
    }
}

// ---------------- prep: encoding vectors + layer 10x10 gates ----------------
__global__ void k_enc(const float* __restrict__ jets, const float* __restrict__ s_scale,
                      const float* __restrict__ dmag, const float* __restrict__ dph,
                      const float* __restrict__ smag, const float* __restrict__ sph) {
    __shared__ float2 B0[100], B1[100], B2[100], B3[100], B4[100];
    __shared__ float red[16];
    int t = threadIdx.x;
    int id = blockIdx.x;

    float r_s, p_s, r_d, p_d;
    if (id < NB * 4) {
        const float* j3 = jets + id * 3;
        float eta = j3[0], ph = j3[1], pt = j3[2];
        float sc = 10.f / (1.f + expf(-s_scale[0])) + 0.01f;
        r_s = eta;      p_s = pt * ph * 0.5f;
        r_d = sc * pt;  p_d = eta;
    } else {
        int lw = id - NB * 4;
        r_s = smag[lw]; p_s = sph[lw];
        r_d = dmag[lw]; p_d = dph[lw];
    }

    float2 z = make_float2(r_s * cosf(p_s), r_s * sinf(p_s));
    if (t < 100) {
        int i = t / 10, j = t % 10;
        float2 g = make_float2(0.f, 0.f);
        if (j == i + 2) {
            float v = sqrtf((float)((i + 1) * (i + 2)));
            g.x = 0.5f * z.x * v;  g.y = -0.5f * z.y * v;
        } else if (i == j + 2) {
            float v = sqrtf((float)((j + 1) * (j + 2)));
            g.x = -0.5f * z.x * v; g.y = -0.5f * z.y * v;
        }
        B0[t] = g;
    }
    __syncthreads();
    expm10(B0, B1, B2, B3, red, t);
    __syncthreads();

    float2 al = make_float2(r_d * cosf(p_d), r_d * sinf(p_d));
    if (t < 100) {
        int i = t / 10, j = t % 10;
        float2 g = make_float2(0.f, 0.f);
        if (i == j + 1) {
            float v = sqrtf((float)(j + 1));
            g.x = al.x * v;  g.y = al.y * v;
        } else if (j == i + 1) {
            float v = sqrtf((float)(i + 1));
            g.x = -al.x * v; g.y = al.y * v;
        }
        B0[t] = g;
    }
    __syncthreads();
    expm10(B0, B4, B2, B3, red, t);
    __syncthreads();

    if (id < NB * 4) {
        if (t < 10) {
            float2 acc = make_float2(0.f, 0.f);
#pragma unroll
            for (int k = 0; k < 10; k++) cmacc(acc, B4[t * 10 + k], B1[k * 10 + 0]);
            g_psi[id * 10 + t] = acc;
        }
    } else {
        if (t < 100) {
            int i = t / 10, j = t % 10;
            float2 acc = make_float2(0.f, 0.f);
#pragma unroll
            for (int k = 0; k < 10; k++) cmacc(acc, B4[i * 10 + k], B1[k * 10 + j]);
            g_Elay[(id - NB * 4) * 100 + t] = acc;
        }
    }
}

// ---------------- prep pipeline: 100x100 expm via parallel launches ---------
__global__ void k_g_init() {
    int m = blockIdx.x;            // 0 = CX, 1 = BS
    int t = threadIdx.x;
    const float PIO4 = 0.7853981633974483f;
    const float SCF = 1.0f / 64.0f;
    for (int e = t; e < 10000; e += blockDim.x) {
        int o = e / 100, in = e % 100;
        int i = o / 10, j = o % 10, k = in / 10, l = in % 10;
        float2 g = make_float2(0.f, 0.f);
        if (m == 0) {
            float x1 = 0.f;
            if (k == i + 1) x1 = sqrtf((float)(i + 1));
            else if (i == k + 1) x1 = sqrtf((float)(k + 1));
            float y1 = 0.f;
            if (l == j + 1) y1 += sqrtf((float)(j + 1));
            if (j == l + 1) y1 -= sqrtf((float)(l + 1));
            g.x = -0.5f * x1 * y1;
        } else {
            float v = 0.f;
            if (k == i + 1 && j == l + 1) v += sqrtf((float)(i + 1)) * sqrtf((float)(l + 1));
            if (i == k + 1 && l == j + 1) v += sqrtf((float)(k + 1)) * sqrtf((float)(j + 1));
            g.y = PIO4 * v;
        }
        g.x *= SCF; g.y *= SCF;
        g_Xm[m][e] = g;
        g_Tp[0][m][e] = g;
        float2 s = g;
        if (o == in) s.x += 1.f;
        g_Sp[0][m][e] = s;
    }
}

__global__ void k_g_taylor(int jterm, int par) {
    extern __shared__ float2 Xs[];                // 10000
    int m = blockIdx.x / 20, rblk = blockIdx.x % 20;
    for (int e = threadIdx.x; e < 10000; e += blockDim.x) Xs[e] = g_Xm[m][e];
    __syncthreads();
    int t = threadIdx.x;
    if (t >= 500) return;
    int row = rblk * 5 + t / 100, col = t % 100;
    const float2* T = g_Tp[par][m];
    float inv = 1.f / (float)jterm;
    float2 acc = make_float2(0.f, 0.f);
    for (int k = 0; k < 100; k++) cmacc(acc, T[row * 100 + k], Xs[k * 100 + col]);
    acc.x *= inv; acc.y *= inv;
    g_Tp[1 - par][m][row * 100 + col] = acc;
    float2 s = g_Sp[0][m][row * 100 + col];
    s.x += acc.x; s.y += acc.y;
    g_Sp[0][m][row * 100 + col] = s;
}

__global__ void k_g_square(int par) {
    extern __shared__ float2 Ss[];                // 10000
    int m = blockIdx.x / 20, rblk = blockIdx.x % 20;
    for (int e = threadIdx.x; e < 10000; e += blockDim.x) Ss[e] = g_Sp[par][m][e];
    __syncthreads();
    int t = threadIdx.x;
    if (t >= 500) return;
    int row = rblk * 5 + t / 100, col = t % 100;
    float2 acc = make_float2(0.f, 0.f);
    for (int k = 0; k < 100; k++) cmacc(acc, Ss[row * 100 + k], Ss[k * 100 + col]);
    g_Sp[1 - par][m][row * 100 + col] = acc;
}

// ---------------- prep: pack duplicated/packed gate tables ------------------
// CX2[kk][o][ll] = (u,u) with u = CX[o][kk*10+ll] (CX exactly real)
// BS4 / E4 entries = (x, x, -y, y)
__global__ void k_pack() {
    int t = blockIdx.x * blockDim.x + threadIdx.x;
    if (t < 10000) {
        int kk = t / 1000, rem = t - kk * 1000;
        int o = rem / 10, ll = rem % 10;
        float u = g_Sp[0][0][o * 100 + kk * 10 + ll].x;
        g_CX2[t] = make_float2(u, u);
    } else if (t < 11900) {
        int e = t - 10000;                    // (N, r, c) over 19 x 10 x 10
        int N = e / 100, rc = e % 100;
        int r = rc / 10, cc = rc % 10;
        int b = d_bsz[N], lo = d_lo[N];
        if (r < b && cc < b) {
            int i = lo + r,  j = N - i;
            int k = lo + cc, l = N - k;
            float2 v = g_Sp[0][1][(i * 10 + j) * 100 + (k * 10 + l)];
            g_BS4[d_off[N] + r * b + cc] = make_float4(v.x, v.x, -v.y, v.y);
        }
    } else if (t < 12700) {
        int e = t - 11900;
        float2 v = g_Elay[e];
        g_E4[e] = make_float4(v.x, v.x, -v.y, v.y);
    }
}

// ---------------- main kernel passes (1024 thr, FFMA2) ----------------------
// Real two-mode CX gate with duplicated-pair U (ulonglong2 = 2 packed pairs).
template<int S1, int S2, int SA, int SB>
__device__ __forceinline__ void pass_cx2(float2* st, const ulonglong2* U2, int tid) {
    unsigned long long acc[10];
    int base = 0, rb = 0;
    if (tid < 1000) {
        rb = tid / 100;
        int sp = tid - rb * 100;
        base = (sp / 10) * SA + (sp % 10) * SB;
#pragma unroll
        for (int q = 0; q < 10; q++) acc[q] = 0ull;
        const unsigned long long* st64 = (const unsigned long long*)st;
#pragma unroll 1
        for (int kk = 0; kk < 10; kk++) {
            unsigned long long xr[10];
#pragma unroll
            for (int ll = 0; ll < 10; ll++) xr[ll] = st64[base + kk * S1 + ll * S2];
            const ulonglong2* Uk = U2 + kk * 500 + rb * 50;
#pragma unroll
            for (int q = 0; q < 10; q++) {
                const ulonglong2* Ur = Uk + q * 5;
                ulonglong2 w0 = Ur[0], w1 = Ur[1], w2 = Ur[2], w3 = Ur[3], w4 = Ur[4];
                fma2(acc[q], w0.x, xr[0]); fma2(acc[q], w0.y, xr[1]);
                fma2(acc[q], w1.x, xr[2]); fma2(acc[q], w1.y, xr[3]);
                fma2(acc[q], w2.x, xr[4]); fma2(acc[q], w2.y, xr[5]);
                fma2(acc[q], w3.x, xr[6]); fma2(acc[q], w3.y, xr[7]);
                fma2(acc[q], w4.x, xr[8]); fma2(acc[q], w4.y, xr[9]);
            }
        }
    }
    __syncthreads();
    if (tid < 1000) {
        unsigned long long* st64w = (unsigned long long*)st;
#pragma unroll
        for (int q = 0; q < 10; q++)
            st64w[base + rb * S1 + q * S2] = acc[q];
    }
    __syncthreads();
}

// BS photon-number-block pass (complex via 2x FFMA2 per term).
template<int SI, int SJ, int SA, int SB>
__device__ __forceinline__ void pass_bs2(float2* st, const ulonglong2* B4, int tid) {
    unsigned long long* st64 = (unsigned long long*)st;
    for (int it = tid; it < 1900; it += NTHR) {
        int N = it / 100; int sp = it - N * 100;
        int b = d_bsz[N], lo = d_lo[N], of = d_off[N];
        int spa = sp / 10;
        int base = spa * SA + (sp - spa * 10) * SB;
        int ilo = base + lo * SI + (N - lo) * SJ;
        const int step = SI - SJ;
        unsigned long long in[10], insw[10];
        for (int c = 0; c < b; c++) { in[c] = st64[ilo + c * step]; insw[c] = swap2(in[c]); }
        const ulonglong2* Bb = B4 + of;
        for (int r = 0; r < b; r++) {
            unsigned long long acc = 0ull;
            const ulonglong2* Br = Bb + r * b;
            for (int c = 0; c < b; c++) {
                ulonglong2 w = Br[c];
                fma2(acc, w.y, insw[c]);   // (-y,y)*(b.y,b.x)
                fma2(acc, w.x, in[c]);     // ( x,x)*(b.x,b.y)
            }
            st64[ilo + r * step] = acc;
        }
    }
    __syncthreads();
}

// Complex single-mode gate via FFMA2.
__device__ __forceinline__ void pass_e2(float2* st, const ulonglong2* E4, int sm, int tid) {
    if (tid < 1000) {
        unsigned long long* st64 = (unsigned long long*)st;
        int base = (tid / sm) * (sm * 10) + (tid % sm);
        unsigned long long in[10], insw[10];
#pragma unroll
        for (int k = 0; k < 10; k++) { in[k] = st64[base + k * sm]; insw[k] = swap2(in[k]); }
#pragma unroll
        for (int i = 0; i < 10; i++) {
            unsigned long long acc = 0ull;
#pragma unroll
            for (int k = 0; k < 10; k++) {
                ulonglong2 w = E4[i * 10 + k];
                fma2(acc, w.y, insw[k]);
                fma2(acc, w.x, in[k]);
            }
            st64[base + i * sm] = acc;
        }
    }
    __syncthreads();
}

// ---------------- main: whole circuit per batch element in SMEM -------------
// SMEM floats: st[20000] | U2[20000] | BS4[2680] | E4[3200]
#define SM_U2  20000
#define SM_BS4 40000
#define SM_E4  42680
#define SM_FLOATS 45880

__global__ void __launch_bounds__(NTHR, 1) k_main(const float* __restrict__ w_dense,
                                                  const float* __restrict__ b_dense,
                                                  float* __restrict__ out) {
    extern __shared__ float shf[];
    float2*     st  = (float2*)shf;
    ulonglong2* U2  = (ulonglong2*)(shf + SM_U2);
    ulonglong2* BS4 = (ulonglong2*)(shf + SM_BS4);
    ulonglong2* E4  = (ulonglong2*)(shf + SM_E4);
    __shared__ float2 psi[40];
    __shared__ float redsh[96];

    int tid = threadIdx.x;
    int b = blockIdx.x;

    // ---- stage tables once ----
    {
        const float4* src = (const float4*)g_CX2;       // 5000 float4
        float4* dst = (float4*)(shf + SM_U2);
        for (int e = tid; e < 5000; e += NTHR) dst[e] = src[e];
    }
    {
        const float4* src = (const float4*)g_BS4;       // 670 float4
        float4* dst = (float4*)(shf + SM_BS4);
        for (int e = tid; e < 670; e += NTHR) dst[e] = src[e];
    }
    {
        const float4* src = (const float4*)g_E4;        // 800 float4
        float4* dst = (float4*)(shf + SM_E4);
        for (int e = tid; e < 800; e += NTHR) dst[e] = src[e];
    }
    if (tid < 40) psi[tid] = g_psi[b * 40 + tid];
    __syncthreads();

    // ---- init: outer product of encoded per-wire vectors ----
    for (int e = tid; e < 10000; e += NTHR) {
        int i0 = e / 1000; int r = e - i0 * 1000;
        int i1 = r / 100;  r -= i1 * 100;
        int i2 = r / 10;   int i3 = r - i2 * 10;
        st[e] = cmul(cmul(psi[i0], psi[10 + i1]), cmul(psi[20 + i2], psi[30 + i3]));
    }
    __syncthreads();

#pragma unroll 1
    for (int L = 0; L < 2; L++) {
        // ---- 6 CX gates (real, FFMA2), reference order ----
        pass_cx2<1000, 100, 10, 1>(st, U2, tid);    // (0,1)
        pass_cx2<1000, 10, 100, 1>(st, U2, tid);    // (0,2)
        pass_cx2<1000, 1, 100, 10>(st, U2, tid);    // (0,3)
        pass_cx2<100, 10, 1000, 1>(st, U2, tid);    // (1,2)
        pass_cx2<100, 1, 1000, 10>(st, U2, tid);    // (1,3)
        pass_cx2<10, 1, 1000, 100>(st, U2, tid);    // (2,3)

        // ---- 4 BS gates (photon-number blocks, FFMA2) ----
        pass_bs2<1000, 100, 10, 1>(st, BS4, tid);   // (0,1)
        pass_bs2<100, 10, 1000, 1>(st, BS4, tid);   // (1,2)
        pass_bs2<10, 1, 1000, 100>(st, BS4, tid);   // (2,3)
        pass_bs2<1, 1000, 100, 10>(st, BS4, tid);   // (3,0)

        // ---- 4 merged single-mode E = D@S gates (FFMA2) ----
        pass_e2(st, E4 + (L * 4 + 0) * 100, 1000, tid);
        pass_e2(st, E4 + (L * 4 + 1) * 100, 100,  tid);
        pass_e2(st, E4 + (L * 4 + 2) * 100, 10,   tid);
        pass_e2(st, E4 + (L * 4 + 3) * 100, 1,    tid);
    }

    // ---- photon-number readout on modes 0..2, dense head ----
    float p0 = 0.f, p1 = 0.f, p2 = 0.f;
    for (int e = tid; e < 10000; e += NTHR) {
        float2 v = st[e];
        float pr = v.x * v.x + v.y * v.y;
        int i0 = e / 1000; int r = e - i0 * 1000;
        int i1 = r / 100;  r -= i1 * 100;
        int i2 = r / 10;
        p0 += pr * (float)i0;
        p1 += pr * (float)i1;
        p2 += pr * (float)i2;
    }
#pragma unroll
    for (int o = 16; o > 0; o >>= 1) {
        p0 += __shfl_down_sync(0xffffffffu, p0, o);
        p1 += __shfl_down_sync(0xffffffffu, p1, o);
        p2 += __shfl_down_sync(0xffffffffu, p2, o);
    }
    int wid = tid >> 5, lane = tid & 31;
    if (lane == 0) { redsh[wid] = p0; redsh[32 + wid] = p1; redsh[64 + wid] = p2; }
    __syncthreads();
    if (tid == 0) {
        float q0 = 0.f, q1 = 0.f, q2 = 0.f;
        for (int w = 0; w < 32; w++) { q0 += redsh[w]; q1 += redsh[32 + w]; q2 += redsh[64 + w]; }
        out[b] = q0 * w_dense[0] + q1 * w_dense[1] + q2 * w_dense[2] + b_dense[0];
    }
}

// ---------------- launch -----------------------------------------------------
extern "C" void kernel_launch(void* const* d_in, const int* in_sizes, int n_in,
                              void* d_out, int out_size) {
    const float* jets    = (const float*)d_in[0];
    const float* s_scale = (const float*)d_in[1];
    const float* dmag    = (const float*)d_in[2];
    const float* dph     = (const float*)d_in[3];
    const float* smag    = (const float*)d_in[4];
    const float* sph     = (const float*)d_in[5];
    const float* w_dense = (const float*)d_in[6];
    const float* b_dense = (const float*)d_in[7];
    float* out = (float*)d_out;

    const int smem_main = SM_FLOATS * 4;   // 183520 bytes
    const int smem_g = 10000 * 8;          // 80000 bytes
    cudaFuncSetAttribute(k_main,     cudaFuncAttributeMaxDynamicSharedMemorySize, smem_main);
    cudaFuncSetAttribute(k_g_taylor, cudaFuncAttributeMaxDynamicSharedMemorySize, smem_g);
    cudaFuncSetAttribute(k_g_square, cudaFuncAttributeMaxDynamicSharedMemorySize, smem_g);

    k_enc<<<NB * 4 + 8, 128>>>(jets, s_scale, dmag, dph, smag, sph);
    k_g_init<<<2, 512>>>();
    for (int j = 2; j <= 8; j++)
        k_g_taylor<<<40, 512, smem_g>>>(j, j & 1);
    for (int it = 0; it < 6; it++)
        k_g_square<<<40, 512, smem_g>>>(it & 1);
    k_pack<<<50, 256>>>();
    k_main<<<NB, NTHR, smem_main>>>(w_dense, b_dense, out);
}

// round 12
// speedup vs baseline: 1.2597x; 1.2597x over previous
#include <cuda_runtime.h>
#include <math.h>

#define NB   2048
#define NTHR 512

// ---------------- global scratch -------------------------------------------
__device__ float2 g_psi[NB * 4 * 10];       // encoded per-wire vectors
__device__ float2 g_Elay[8 * 100];          // merged layer 10x10 complex gates (D@S)
__device__ __align__(16) float2 g_Xm[2][10000];   // scaled generators (CX, BS)
__device__ __align__(16) float2 g_Tp[2][2][10000];// Taylor term ping-pong
__device__ __align__(16) float2 g_Sp[2][2][10000];// partial sum ping-pong
__device__ __align__(16) float  g_CXp[12000];     // CX real, packed [k1][o][12]
__device__ float2 g_BSb[670];                     // BS photon-number blocks packed

// BS block tables
__constant__ int d_bsz[19] = {1,2,3,4,5,6,7,8,9,10,9,8,7,6,5,4,3,2,1};
__constant__ int d_off[19] = {0,1,5,14,30,55,91,140,204,285,385,466,530,579,615,640,656,665,669};
__constant__ int d_lo[19]  = {0,0,0,0,0,0,0,0,0,0,1,2,3,4,5,6,7,8,9};

// ---------------- complex helpers ------------------------------------------
__device__ __forceinline__ float2 cmul(float2 a, float2 b) {
    return make_float2(a.x * b.x - a.y * b.y, a.x * b.y + a.y * b.x);
}
__device__ __forceinline__ void cmacc(float2& acc, float2 a, float2 b) {
    acc.x = fmaf(a.x, b.x, fmaf(-a.y, b.y, acc.x));
    acc.y = fmaf(a.x, b.y, fmaf( a.y, b.x, acc.y));
}

// ---------------- 10x10 expm (block-cooperative, >=128 thr) -----------------
__device__ void expm10(float2* X, float2* S, float2* T, float2* T2, float* red, int t) {
    if (t < 10) {
        float s = 0.f;
        for (int j = 0; j < 10; j++) { float2 v = X[t * 10 + j]; s += fabsf(v.x) + fabsf(v.y); }
        red[t] = s;
    }
    __syncthreads();
    if (t == 0) {
        float m = 0.f;
        for (int i = 0; i < 10; i++) m = fmaxf(m, red[i]);
        int s = 0;
        while (m > 0.5f && s < 40) { m *= 0.5f; s++; }
        red[10] = (float)s;
    }
    __syncthreads();
    int s = (int)red[10];
    float sc = ldexpf(1.f, -s);
    if (t < 100) {
        X[t].x *= sc; X[t].y *= sc;
        T[t] = X[t];
        float2 v = X[t];
        if (t % 11 == 0) v.x += 1.f;
        S[t] = v;
    }
    __syncthreads();
    for (int j = 2; j <= 13; j++) {
        float inv = 1.f / (float)j;
        if (t < 100) {
            int i = t / 10, c = t % 10;
            float2 acc = make_float2(0.f, 0.f);
#pragma unroll
            for (int k = 0; k < 10; k++) cmacc(acc, T[i * 10 + k], X[k * 10 + c]);
            T2[t] = make_float2(acc.x * inv, acc.y * inv);
        }
        __syncthreads();
        if (t < 100) { T[t] = T2[t]; S[t].x += T2[t].x; S[t].y += T2[t].y; }
        __syncthreads();
    }
    for (int it = 0; it < s; it++) {
        if (t < 100) {
            int i = t / 10, c = t % 10;
            float2 acc = make_float2(0.f, 0.f);
#pragma unroll
            for (int k = 0; k < 10; k++) cmacc(acc, S[i * 10 + k], S[k * 10 + c]);
            T2[t] = acc;
        }
        __syncthreads();
        if (t < 100) S[t] = T2[t];
        __syncthreads();
    }
}

// ---------------- prep: encoding vectors + layer 10x10 gates ----------------
__global__ void k_enc(const float* __restrict__ jets, const float* __restrict__ s_scale,
                      const float* __restrict__ dmag, const float* __restrict__ dph,
                      const float* __restrict__ smag, const float* __restrict__ sph) {
    __shared__ float2 B0[100], B1[100], B2[100], B3[100], B4[100];
    __shared__ float red[16];
    int t = threadIdx.x;
    int id = blockIdx.x;

    float r_s, p_s, r_d, p_d;
    if (id < NB * 4) {
        const float* j3 = jets + id * 3;
        float eta = j3[0], ph = j3[1], pt = j3[2];
        float sc = 10.f / (1.f + expf(-s_scale[0])) + 0.01f;
        r_s = eta;      p_s = pt * ph * 0.5f;
        r_d = sc * pt;  p_d = eta;
    } else {
        int lw = id - NB * 4;
        r_s = smag[lw]; p_s = sph[lw];
        r_d = dmag[lw]; p_d = dph[lw];
    }

    float2 z = make_float2(r_s * cosf(p_s), r_s * sinf(p_s));
    if (t < 100) {
        int i = t / 10, j = t % 10;
        float2 g = make_float2(0.f, 0.f);
        if (j == i + 2) {
            float v = sqrtf((float)((i + 1) * (i + 2)));
            g.x = 0.5f * z.x * v;  g.y = -0.5f * z.y * v;
        } else if (i == j + 2) {
            float v = sqrtf((float)((j + 1) * (j + 2)));
            g.x = -0.5f * z.x * v; g.y = -0.5f * z.y * v;
        }
        B0[t] = g;
    }
    __syncthreads();
    expm10(B0, B1, B2, B3, red, t);
    __syncthreads();

    float2 al = make_float2(r_d * cosf(p_d), r_d * sinf(p_d));
    if (t < 100) {
        int i = t / 10, j = t % 10;
        float2 g = make_float2(0.f, 0.f);
        if (i == j + 1) {
            float v = sqrtf((float)(j + 1));
            g.x = al.x * v;  g.y = al.y * v;
        } else if (j == i + 1) {
            float v = sqrtf((float)(i + 1));
            g.x = -al.x * v; g.y = al.y * v;
        }
        B0[t] = g;
    }
    __syncthreads();
    expm10(B0, B4, B2, B3, red, t);
    __syncthreads();

    if (id < NB * 4) {
        if (t < 10) {
            float2 acc = make_float2(0.f, 0.f);
#pragma unroll
            for (int k = 0; k < 10; k++) cmacc(acc, B4[t * 10 + k], B1[k * 10 + 0]);
            g_psi[id * 10 + t] = acc;
        }
    } else {
        if (t < 100) {
            int i = t / 10, j = t % 10;
            float2 acc = make_float2(0.f, 0.f);
#pragma unroll
            for (int k = 0; k < 10; k++) cmacc(acc, B4[i * 10 + k], B1[k * 10 + j]);
            g_Elay[(id - NB * 4) * 100 + t] = acc;
        }
    }
}

// ---------------- prep pipeline: 100x100 expm via parallel launches ---------
__global__ void k_g_init() {
    int m = blockIdx.x;            // 0 = CX, 1 = BS
    int t = threadIdx.x;
    const float PIO4 = 0.7853981633974483f;
    const float SCF = 1.0f / 64.0f;
    for (int e = t; e < 10000; e += blockDim.x) {
        int o = e / 100, in = e % 100;
        int i = o / 10, j = o % 10, k = in / 10, l = in % 10;
        float2 g = make_float2(0.f, 0.f);
        if (m == 0) {
            float x1 = 0.f;
            if (k == i + 1) x1 = sqrtf((float)(i + 1));
            else if (i == k + 1) x1 = sqrtf((float)(k + 1));
            float y1 = 0.f;
            if (l == j + 1) y1 += sqrtf((float)(j + 1));
            if (j == l + 1) y1 -= sqrtf((float)(l + 1));
            g.x = -0.5f * x1 * y1;
        } else {
            float v = 0.f;
            if (k == i + 1 && j == l + 1) v += sqrtf((float)(i + 1)) * sqrtf((float)(l + 1));
            if (i == k + 1 && l == j + 1) v += sqrtf((float)(k + 1)) * sqrtf((float)(j + 1));
            g.y = PIO4 * v;
        }
        g.x *= SCF; g.y *= SCF;
        g_Xm[m][e] = g;
        g_Tp[0][m][e] = g;
        float2 s = g;
        if (o == in) s.x += 1.f;
        g_Sp[0][m][e] = s;
    }
}

__global__ void k_g_taylor(int jterm, int par) {
    extern __shared__ float2 Xs[];                // 10000
    int m = blockIdx.x / 20, rblk = blockIdx.x % 20;
    for (int e = threadIdx.x; e < 10000; e += blockDim.x) Xs[e] = g_Xm[m][e];
    __syncthreads();
    int t = threadIdx.x;
    if (t >= 500) return;
    int row = rblk * 5 + t / 100, col = t % 100;
    const float2* T = g_Tp[par][m];
    float inv = 1.f / (float)jterm;
    float2 acc = make_float2(0.f, 0.f);
    for (int k = 0; k < 100; k++) cmacc(acc, T[row * 100 + k], Xs[k * 100 + col]);
    acc.x *= inv; acc.y *= inv;
    g_Tp[1 - par][m][row * 100 + col] = acc;
    float2 s = g_Sp[0][m][row * 100 + col];
    s.x += acc.x; s.y += acc.y;
    g_Sp[0][m][row * 100 + col] = s;
}

__global__ void k_g_square(int par) {
    extern __shared__ float2 Ss[];                // 10000
    int m = blockIdx.x / 20, rblk = blockIdx.x % 20;
    for (int e = threadIdx.x; e < 10000; e += blockDim.x) Ss[e] = g_Sp[par][m][e];
    __syncthreads();
    int t = threadIdx.x;
    if (t >= 500) return;
    int row = rblk * 5 + t / 100, col = t % 100;
    float2 acc = make_float2(0.f, 0.f);
    for (int k = 0; k < 100; k++) cmacc(acc, Ss[row * 100 + k], Ss[k * 100 + col]);
    g_Sp[1 - par][m][row * 100 + col] = acc;
}

// ---------------- prep: pack CX real [k1][o][12] + BS blocks ----------------
__global__ void k_pack() {
    int t = blockIdx.x * blockDim.x + threadIdx.x;
    if (t < 12000) {
        int kk = t / 1200, rem = t % 1200;
        int o = rem / 12, ll = rem % 12;
        g_CXp[t] = (ll < 10) ? g_Sp[0][0][o * 100 + kk * 10 + ll].x : 0.f;
    } else if (t < 13900) {
        int e = t - 12000;
        int N = e / 100, rc = e % 100;
        int r = rc / 10, cc = rc % 10;
        int b = d_bsz[N], lo = d_lo[N];
        if (r < b && cc < b) {
            int i = lo + r,  j = N - i;
            int k = lo + cc, l = N - k;
            g_BSb[d_off[N] + r * b + cc] = g_Sp[0][1][(i * 10 + j) * 100 + (k * 10 + l)];
        }
    }
}

// ---------------- main kernel passes (512 thr, 2 CTAs/SM) -------------------
// Real two-mode CX gate: 500 active threads, each owns 20 outputs (2 rows).
// U read from GLOBAL (warp-uniform broadcast LDG; aligned float4/float2).
template<int S1, int S2, int SA, int SB>
__device__ __forceinline__ void pass_cx(float2* st, int tid) {
    float2 acc[20];
    int base = 0, rb = 0;
    if (tid < 500) {
        rb = tid / 100;
        int sp = tid - rb * 100;
        base = (sp / 10) * SA + (sp % 10) * SB;
#pragma unroll
        for (int q = 0; q < 20; q++) acc[q] = make_float2(0.f, 0.f);
#pragma unroll 1
        for (int kk = 0; kk < 10; kk++) {
            const float* UK = g_CXp + kk * 1200 + rb * 240;   // rows 2rb..2rb+1 (20 outputs)
            const float2* rowp = st + base + kk * S1;
            float2 x0, x1, x2, x3;
            // chunk A: inputs ll = 0..3
            x0 = rowp[0]; x1 = rowp[S2]; x2 = rowp[2 * S2]; x3 = rowp[3 * S2];
#pragma unroll
            for (int q = 0; q < 20; q++) {
                float4 u = *(const float4*)(UK + q * 12);
                acc[q].x = fmaf(u.x, x0.x, acc[q].x); acc[q].y = fmaf(u.x, x0.y, acc[q].y);
                acc[q].x = fmaf(u.y, x1.x, acc[q].x); acc[q].y = fmaf(u.y, x1.y, acc[q].y);
                acc[q].x = fmaf(u.z, x2.x, acc[q].x); acc[q].y = fmaf(u.z, x2.y, acc[q].y);
                acc[q].x = fmaf(u.w, x3.x, acc[q].x); acc[q].y = fmaf(u.w, x3.y, acc[q].y);
            }
            // chunk B: inputs ll = 4..7
            x0 = rowp[4 * S2]; x1 = rowp[5 * S2]; x2 = rowp[6 * S2]; x3 = rowp[7 * S2];
#pragma unroll
            for (int q = 0; q < 20; q++) {
                float4 u = *(const float4*)(UK + q * 12 + 4);
                acc[q].x = fmaf(u.x, x0.x, acc[q].x); acc[q].y = fmaf(u.x, x0.y, acc[q].y);
                acc[q].x = fmaf(u.y, x1.x, acc[q].x); acc[q].y = fmaf(u.y, x1.y, acc[q].y);
                acc[q].x = fmaf(u.z, x2.x, acc[q].x); acc[q].y = fmaf(u.z, x2.y, acc[q].y);
                acc[q].x = fmaf(u.w, x3.x, acc[q].x); acc[q].y = fmaf(u.w, x3.y, acc[q].y);
            }
            // chunk C: inputs ll = 8..9
            x0 = rowp[8 * S2]; x1 = rowp[9 * S2];
#pragma unroll
            for (int q = 0; q < 20; q++) {
                float2 u = *(const float2*)(UK + q * 12 + 8);
                acc[q].x = fmaf(u.x, x0.x, acc[q].x); acc[q].y = fmaf(u.x, x0.y, acc[q].y);
                acc[q].x = fmaf(u.y, x1.x, acc[q].x); acc[q].y = fmaf(u.y, x1.y, acc[q].y);
            }
        }
    }
    __syncthreads();
    if (tid < 500) {
#pragma unroll
        for (int q = 0; q < 20; q++) {
            int o = rb * 20 + q;
            st[base + (o / 10) * S1 + (o % 10) * S2] = acc[q];
        }
    }
    __syncthreads();
}

// BS photon-number-block pass (gates from global).
template<int SI, int SJ, int SA, int SB>
__device__ __forceinline__ void pass_bs(float2* st, int tid) {
    for (int it = tid; it < 1900; it += NTHR) {
        int N = it / 100; int sp = it - N * 100;
        int b = d_bsz[N], lo = d_lo[N], of = d_off[N];
        int spa = sp / 10;
        int base = spa * SA + (sp - spa * 10) * SB;
        int ilo = base + lo * SI + (N - lo) * SJ;
        const int step = SI - SJ;
        float2 in[10];
        for (int c = 0; c < b; c++) in[c] = st[ilo + c * step];
        const float2* Bb = g_BSb + of;
        for (int r = 0; r < b; r++) {
            float2 acc = make_float2(0.f, 0.f);
            const float2* Br = Bb + r * b;
            for (int c = 0; c < b; c++) cmacc(acc, Br[c], in[c]);
            st[ilo + r * step] = acc;
        }
    }
    __syncthreads();
}

// Complex single-mode gate (gate from global), in-place per fiber.
__device__ __forceinline__ void pass_e(float2* st, const float2* __restrict__ E, int sm, int tid) {
    for (int f = tid; f < 1000; f += NTHR) {
        int base = (f / sm) * (sm * 10) + (f % sm);
        float2 in[10];
#pragma unroll
        for (int k = 0; k < 10; k++) in[k] = st[base + k * sm];
#pragma unroll
        for (int i = 0; i < 10; i++) {
            float2 a = make_float2(0.f, 0.f);
#pragma unroll
            for (int k = 0; k < 10; k++) cmacc(a, E[i * 10 + k], in[k]);
            st[base + i * sm] = a;
        }
    }
    __syncthreads();
}

// ---------------- main: whole circuit per batch element in SMEM -------------
// Dynamic smem = state only (80000 B) -> 2 CTAs/SM; gates stream from L1.
__global__ void __launch_bounds__(NTHR, 2) k_main(const float* __restrict__ w_dense,
                                                  const float* __restrict__ b_dense,
                                                  float* __restrict__ out) {
    extern __shared__ float2 st[];              // 10000
    __shared__ float2 psi[40];
    __shared__ float redsh[48];

    int tid = threadIdx.x;
    int b = blockIdx.x;

    if (tid < 40) psi[tid] = g_psi[b * 40 + tid];
    __syncthreads();

    // ---- init: outer product of encoded per-wire vectors ----
    for (int e = tid; e < 10000; e += NTHR) {
        int i0 = e / 1000; int r = e - i0 * 1000;
        int i1 = r / 100;  r -= i1 * 100;
        int i2 = r / 10;   int i3 = r - i2 * 10;
        st[e] = cmul(cmul(psi[i0], psi[10 + i1]), cmul(psi[20 + i2], psi[30 + i3]));
    }
    __syncthreads();

#pragma unroll 1
    for (int L = 0; L < 2; L++) {
        // ---- 6 CX gates (real dense), reference order ----
        pass_cx<1000, 100, 10, 1>(st, tid);    // (0,1)
        pass_cx<1000, 10, 100, 1>(st, tid);    // (0,2)
        pass_cx<1000, 1, 100, 10>(st, tid);    // (0,3)
        pass_cx<100, 10, 1000, 1>(st, tid);    // (1,2)
        pass_cx<100, 1, 1000, 10>(st, tid);    // (1,3)
        pass_cx<10, 1, 1000, 100>(st, tid);    // (2,3)

        // ---- 4 BS gates (photon-number blocks) ----
        pass_bs<1000, 100, 10, 1>(st, tid);    // (0,1)
        pass_bs<100, 10, 1000, 1>(st, tid);    // (1,2)
        pass_bs<10, 1, 1000, 100>(st, tid);    // (2,3)
        pass_bs<1, 1000, 100, 10>(st, tid);    // (3,0)

        // ---- 4 merged single-mode E = D@S gates ----
        pass_e(st, g_Elay + (L * 4 + 0) * 100, 1000, tid);
        pass_e(st, g_Elay + (L * 4 + 1) * 100, 100,  tid);
        pass_e(st, g_Elay + (L * 4 + 2) * 100, 10,   tid);
        pass_e(st, g_Elay + (L * 4 + 3) * 100, 1,    tid);
    }

    // ---- photon-number readout on modes 0..2, dense head ----
    float p0 = 0.f, p1 = 0.f, p2 = 0.f;
    for (int e = tid; e < 10000; e += NTHR) {
        float2 v = st[e];
        float pr = v.x * v.x + v.y * v.y;
        int i0 = e / 1000; int r = e - i0 * 1000;
        int i1 = r / 100;  r -= i1 * 100;
        int i2 = r / 10;
        p0 += pr * (float)i0;
        p1 += pr * (float)i1;
        p2 += pr * (float)i2;
    }
#pragma unroll
    for (int o = 16; o > 0; o >>= 1) {
        p0 += __shfl_down_sync(0xffffffffu, p0, o);
        p1 += __shfl_down_sync(0xffffffffu, p1, o);
        p2 += __shfl_down_sync(0xffffffffu, p2, o);
    }
    int wid = tid >> 5, lane = tid & 31;
    if (lane == 0) { redsh[wid] = p0; redsh[16 + wid] = p1; redsh[32 + wid] = p2; }
    __syncthreads();
    if (tid == 0) {
        float q0 = 0.f, q1 = 0.f, q2 = 0.f;
        for (int w = 0; w < 16; w++) { q0 += redsh[w]; q1 += redsh[16 + w]; q2 += redsh[32 + w]; }
        out[b] = q0 * w_dense[0] + q1 * w_dense[1] + q2 * w_dense[2] + b_dense[0];
    }
}

// ---------------- launch -----------------------------------------------------
extern "C" void kernel_launch(void* const* d_in, const int* in_sizes, int n_in,
                              void* d_out, int out_size) {
    const float* jets    = (const float*)d_in[0];
    const float* s_scale = (const float*)d_in[1];
    const float* dmag    = (const float*)d_in[2];
    const float* dph     = (const float*)d_in[3];
    const float* smag    = (const float*)d_in[4];
    const float* sph     = (const float*)d_in[5];
    const float* w_dense = (const float*)d_in[6];
    const float* b_dense = (const float*)d_in[7];
    float* out = (float*)d_out;

    const int smem_main = 10000 * 8;       // 80000 bytes (state only) -> 2 CTAs/SM
    const int smem_g = 10000 * 8;          // 80000 bytes
    cudaFuncSetAttribute(k_main,     cudaFuncAttributeMaxDynamicSharedMemorySize, smem_main);
    cudaFuncSetAttribute(k_g_taylor, cudaFuncAttributeMaxDynamicSharedMemorySize, smem_g);
    cudaFuncSetAttribute(k_g_square, cudaFuncAttributeMaxDynamicSharedMemorySize, smem_g);

    k_enc<<<NB * 4 + 8, 128>>>(jets, s_scale, dmag, dph, smag, sph);
    k_g_init<<<2, 512>>>();
    for (int j = 2; j <= 8; j++)
        k_g_taylor<<<40, 512, smem_g>>>(j, j & 1);
    for (int it = 0; it < 6; it++)
        k_g_square<<<40, 512, smem_g>>>(it & 1);
    k_pack<<<55, 256>>>();
    k_main<<<NB, NTHR, smem_main>>>(w_dense, b_dense, out);
}

// round 13
// speedup vs baseline: 2.3044x; 1.8293x over previous
#include <cuda_runtime.h>
#include <math.h>

#define NB   2048
#define NTHR 1024

// ---------------- global scratch -------------------------------------------
__device__ float2 g_psi[NB * 4 * 10];       // encoded per-wire vectors
__device__ float2 g_Elay[8 * 100];          // merged layer 10x10 complex gates (D@S)
__device__ __align__(16) float2 g_Xm[2][10000];   // scaled generators (CX, BS)
__device__ __align__(16) float2 g_Tp[2][2][10000];// Taylor term ping-pong
__device__ __align__(16) float2 g_Sp[2][2][10000];// partial sum ping-pong
__device__ __align__(16) float  g_CXp[12000];     // CX real, packed [k1][o][12]
__device__ float2 g_BSb[670];                     // BS photon-number blocks packed

// BS block tables
__constant__ int d_bsz[19] = {1,2,3,4,5,6,7,8,9,10,9,8,7,6,5,4,3,2,1};
__constant__ int d_off[19] = {0,1,5,14,30,55,91,140,204,285,385,466,530,579,615,640,656,665,669};
__constant__ int d_lo[19]  = {0,0,0,0,0,0,0,0,0,0,1,2,3,4,5,6,7,8,9};

// ---------------- complex helpers ------------------------------------------
__device__ __forceinline__ float2 cmul(float2 a, float2 b) {
    return make_float2(a.x * b.x - a.y * b.y, a.x * b.y + a.y * b.x);
}
__device__ __forceinline__ void cmacc(float2& acc, float2 a, float2 b) {
    acc.x = fmaf(a.x, b.x, fmaf(-a.y, b.y, acc.x));
    acc.y = fmaf(a.x, b.y, fmaf( a.y, b.x, acc.y));
}

// ---------------- 10x10 expm (block-cooperative, >=128 thr) -----------------
__device__ void expm10(float2* X, float2* S, float2* T, float2* T2, float* red, int t) {
    if (t < 10) {
        float s = 0.f;
        for (int j = 0; j < 10; j++) { float2 v = X[t * 10 + j]; s += fabsf(v.x) + fabsf(v.y); }
        red[t] = s;
    }
    __syncthreads();
    if (t == 0) {
        float m = 0.f;
        for (int i = 0; i < 10; i++) m = fmaxf(m, red[i]);
        int s = 0;
        while (m > 0.5f && s < 40) { m *= 0.5f; s++; }
        red[10] = (float)s;
    }
    __syncthreads();
    int s = (int)red[10];
    float sc = ldexpf(1.f, -s);
    if (t < 100) {
        X[t].x *= sc; X[t].y *= sc;
        T[t] = X[t];
        float2 v = X[t];
        if (t % 11 == 0) v.x += 1.f;
        S[t] = v;
    }
    __syncthreads();
    for (int j = 2; j <= 13; j++) {
        float inv = 1.f / (float)j;
        if (t < 100) {
            int i = t / 10, c = t % 10;
            float2 acc = make_float2(0.f, 0.f);
#pragma unroll
            for (int k = 0; k < 10; k++) cmacc(acc, T[i * 10 + k], X[k * 10 + c]);
            T2[t] = make_float2(acc.x * inv, acc.y * inv);
        }
        __syncthreads();
        if (t < 100) { T[t] = T2[t]; S[t].x += T2[t].x; S[t].y += T2[t].y; }
        __syncthreads();
    }
    for (int it = 0; it < s; it++) {
        if (t < 100) {
            int i = t / 10, c = t % 10;
            float2 acc = make_float2(0.f, 0.f);
#pragma unroll
            for (int k = 0; k < 10; k++) cmacc(acc, S[i * 10 + k], S[k * 10 + c]);
            T2[t] = acc;
        }
        __syncthreads();
        if (t < 100) S[t] = T2[t];
        __syncthreads();
    }
}

// ---------------- prep: encoding vectors + layer 10x10 gates ----------------
__global__ void k_enc(const float* __restrict__ jets, const float* __restrict__ s_scale,
                      const float* __restrict__ dmag, const float* __restrict__ dph,
                      const float* __restrict__ smag, const float* __restrict__ sph) {
    __shared__ float2 B0[100], B1[100], B2[100], B3[100], B4[100];
    __shared__ float red[16];
    int t = threadIdx.x;
    int id = blockIdx.x;

    float r_s, p_s, r_d, p_d;
    if (id < NB * 4) {
        const float* j3 = jets + id * 3;
        float eta = j3[0], ph = j3[1], pt = j3[2];
        float sc = 10.f / (1.f + expf(-s_scale[0])) + 0.01f;
        r_s = eta;      p_s = pt * ph * 0.5f;
        r_d = sc * pt;  p_d = eta;
    } else {
        int lw = id - NB * 4;
        r_s = smag[lw]; p_s = sph[lw];
        r_d = dmag[lw]; p_d = dph[lw];
    }

    float2 z = make_float2(r_s * cosf(p_s), r_s * sinf(p_s));
    if (t < 100) {
        int i = t / 10, j = t % 10;
        float2 g = make_float2(0.f, 0.f);
        if (j == i + 2) {
            float v = sqrtf((float)((i + 1) * (i + 2)));
            g.x = 0.5f * z.x * v;  g.y = -0.5f * z.y * v;
        } else if (i == j + 2) {
            float v = sqrtf((float)((j + 1) * (j + 2)));
            g.x = -0.5f * z.x * v; g.y = -0.5f * z.y * v;
        }
        B0[t] = g;
    }
    __syncthreads();
    expm10(B0, B1, B2, B3, red, t);
    __syncthreads();

    float2 al = make_float2(r_d * cosf(p_d), r_d * sinf(p_d));
    if (t < 100) {
        int i = t / 10, j = t % 10;
        float2 g = make_float2(0.f, 0.f);
        if (i == j + 1) {
            float v = sqrtf((float)(j + 1));
            g.x = al.x * v;  g.y = al.y * v;
        } else if (j == i + 1) {
            float v = sqrtf((float)(i + 1));
            g.x = -al.x * v; g.y = al.y * v;
        }
        B0[t] = g;
    }
    __syncthreads();
    expm10(B0, B4, B2, B3, red, t);
    __syncthreads();

    if (id < NB * 4) {
        if (t < 10) {
            float2 acc = make_float2(0.f, 0.f);
#pragma unroll
            for (int k = 0; k < 10; k++) cmacc(acc, B4[t * 10 + k], B1[k * 10 + 0]);
            g_psi[id * 10 + t] = acc;
        }
    } else {
        if (t < 100) {
            int i = t / 10, j = t % 10;
            float2 acc = make_float2(0.f, 0.f);
#pragma unroll
            for (int k = 0; k < 10; k++) cmacc(acc, B4[i * 10 + k], B1[k * 10 + j]);
            g_Elay[(id - NB * 4) * 100 + t] = acc;
        }
    }
}

// ---------------- prep pipeline: 100x100 expm via parallel launches ---------
// Fixed scaling 1/64 (scaled norms <=0.32) + Taylor terms 2..8 + 6 squarings.
__global__ void k_g_init() {
    int m = blockIdx.x;            // 0 = CX, 1 = BS
    int t = threadIdx.x;
    const float PIO4 = 0.7853981633974483f;
    const float SCF = 1.0f / 64.0f;
    for (int e = t; e < 10000; e += blockDim.x) {
        int o = e / 100, in = e % 100;
        int i = o / 10, j = o % 10, k = in / 10, l = in % 10;
        float2 g = make_float2(0.f, 0.f);
        if (m == 0) {
            float x1 = 0.f;
            if (k == i + 1) x1 = sqrtf((float)(i + 1));
            else if (i == k + 1) x1 = sqrtf((float)(k + 1));
            float y1 = 0.f;
            if (l == j + 1) y1 += sqrtf((float)(j + 1));
            if (j == l + 1) y1 -= sqrtf((float)(l + 1));
            g.x = -0.5f * x1 * y1;
        } else {
            float v = 0.f;
            if (k == i + 1 && j == l + 1) v += sqrtf((float)(i + 1)) * sqrtf((float)(l + 1));
            if (i == k + 1 && l == j + 1) v += sqrtf((float)(k + 1)) * sqrtf((float)(j + 1));
            g.y = PIO4 * v;
        }
        g.x *= SCF; g.y *= SCF;
        g_Xm[m][e] = g;
        g_Tp[0][m][e] = g;
        float2 s = g;
        if (o == in) s.x += 1.f;
        g_Sp[0][m][e] = s;
    }
}

__global__ void k_g_taylor(int jterm, int par) {
    extern __shared__ float2 Xs[];                // 10000
    int m = blockIdx.x / 20, rblk = blockIdx.x % 20;
    for (int e = threadIdx.x; e < 10000; e += blockDim.x) Xs[e] = g_Xm[m][e];
    __syncthreads();
    int t = threadIdx.x;
    if (t >= 500) return;
    int row = rblk * 5 + t / 100, col = t % 100;
    const float2* T = g_Tp[par][m];
    float inv = 1.f / (float)jterm;
    float2 acc = make_float2(0.f, 0.f);
    for (int k = 0; k < 100; k++) cmacc(acc, T[row * 100 + k], Xs[k * 100 + col]);
    acc.x *= inv; acc.y *= inv;
    g_Tp[1 - par][m][row * 100 + col] = acc;
    float2 s = g_Sp[0][m][row * 100 + col];
    s.x += acc.x; s.y += acc.y;
    g_Sp[0][m][row * 100 + col] = s;
}

__global__ void k_g_square(int par) {
    extern __shared__ float2 Ss[];                // 10000
    int m = blockIdx.x / 20, rblk = blockIdx.x % 20;
    for (int e = threadIdx.x; e < 10000; e += blockDim.x) Ss[e] = g_Sp[par][m][e];
    __syncthreads();
    int t = threadIdx.x;
    if (t >= 500) return;
    int row = rblk * 5 + t / 100, col = t % 100;
    float2 acc = make_float2(0.f, 0.f);
    for (int k = 0; k < 100; k++) cmacc(acc, Ss[row * 100 + k], Ss[k * 100 + col]);
    g_Sp[1 - par][m][row * 100 + col] = acc;
}

// ---------------- prep: pack CX real [k1][o][12] + BS blocks ----------------
__global__ void k_pack() {
    int t = blockIdx.x * blockDim.x + threadIdx.x;
    if (t < 12000) {
        int kk = t / 1200, rem = t % 1200;
        int o = rem / 12, ll = rem % 12;
        g_CXp[t] = (ll < 10) ? g_Sp[0][0][o * 100 + kk * 10 + ll].x : 0.f;
    } else if (t < 13900) {
        int e = t - 12000;
        int N = e / 100, rc = e % 100;
        int r = rc / 10, cc = rc % 10;
        int b = d_bsz[N], lo = d_lo[N];
        if (r < b && cc < b) {
            int i = lo + r,  j = N - i;
            int k = lo + cc, l = N - k;
            g_BSb[d_off[N] + r * b + cc] = g_Sp[0][1][(i * 10 + j) * 100 + (k * 10 + l)];
        }
    }
}

// ---------------- main kernel passes (1024 thr, smem tables; R6-proven) -----
// Real two-mode CX gate. U packed [k1][o][12] in smem; each thread: 10 outputs.
template<int S1, int S2, int SA, int SB>
__device__ __forceinline__ void pass_cx(float2* st, const float* Up, int tid) {
    float2 acc[10];
    int base = 0, rb = 0;
    if (tid < 1000) {
        rb = tid / 100;
        int sp = tid - rb * 100;
        base = (sp / 10) * SA + (sp % 10) * SB;
#pragma unroll
        for (int q = 0; q < 10; q++) acc[q] = make_float2(0.f, 0.f);
#pragma unroll 1
        for (int kk = 0; kk < 10; kk++) {
            float2 xr[10];
            const float2* rowp = st + base + kk * S1;
#pragma unroll
            for (int ll = 0; ll < 10; ll++) xr[ll] = rowp[ll * S2];
            const float* Uk = Up + kk * 1200 + rb * 120;
#pragma unroll
            for (int q = 0; q < 10; q++) {
                const float* Ur = Uk + q * 12;
                float4 u0 = *(const float4*)Ur;
                float4 u1 = *(const float4*)(Ur + 4);
                float2 u2 = *(const float2*)(Ur + 8);
                float ax = acc[q].x, ay = acc[q].y;
                ax = fmaf(u0.x, xr[0].x, ax); ay = fmaf(u0.x, xr[0].y, ay);
                ax = fmaf(u0.y, xr[1].x, ax); ay = fmaf(u0.y, xr[1].y, ay);
                ax = fmaf(u0.z, xr[2].x, ax); ay = fmaf(u0.z, xr[2].y, ay);
                ax = fmaf(u0.w, xr[3].x, ax); ay = fmaf(u0.w, xr[3].y, ay);
                ax = fmaf(u1.x, xr[4].x, ax); ay = fmaf(u1.x, xr[4].y, ay);
                ax = fmaf(u1.y, xr[5].x, ax); ay = fmaf(u1.y, xr[5].y, ay);
                ax = fmaf(u1.z, xr[6].x, ax); ay = fmaf(u1.z, xr[6].y, ay);
                ax = fmaf(u1.w, xr[7].x, ax); ay = fmaf(u1.w, xr[7].y, ay);
                ax = fmaf(u2.x, xr[8].x, ax); ay = fmaf(u2.x, xr[8].y, ay);
                ax = fmaf(u2.y, xr[9].x, ax); ay = fmaf(u2.y, xr[9].y, ay);
                acc[q].x = ax; acc[q].y = ay;
            }
        }
    }
    __syncthreads();
    if (tid < 1000) {
#pragma unroll
        for (int q = 0; q < 10; q++)
            st[base + rb * S1 + q * S2] = acc[q];
    }
    __syncthreads();
}

// BS photon-number-block pass.
template<int SI, int SJ, int SA, int SB>
__device__ __forceinline__ void pass_bs(float2* st, const float2* BSb, int tid) {
    for (int it = tid; it < 1900; it += NTHR) {
        int N = it / 100; int sp = it - N * 100;
        int b = d_bsz[N], lo = d_lo[N], of = d_off[N];
        int spa = sp / 10;
        int base = spa * SA + (sp - spa * 10) * SB;
        int ilo = base + lo * SI + (N - lo) * SJ;
        const int step = SI - SJ;
        float2 in[10];
        for (int c = 0; c < b; c++) in[c] = st[ilo + c * step];
        const float2* Bb = BSb + of;
        for (int r = 0; r < b; r++) {
            float2 acc = make_float2(0.f, 0.f);
            const float2* Br = Bb + r * b;
            for (int c = 0; c < b; c++) cmacc(acc, Br[c], in[c]);
            st[ilo + r * step] = acc;
        }
    }
    __syncthreads();
}

// Complex single-mode gate, in-place per fiber.
__device__ __forceinline__ void pass_e(float2* st, const float2* E, int sm, int tid) {
    if (tid < 1000) {
        int base = (tid / sm) * (sm * 10) + (tid % sm);
        float2 in[10];
#pragma unroll
        for (int k = 0; k < 10; k++) in[k] = st[base + k * sm];
#pragma unroll
        for (int i = 0; i < 10; i++) {
            float2 a = make_float2(0.f, 0.f);
#pragma unroll
            for (int k = 0; k < 10; k++) cmacc(a, E[i * 10 + k], in[k]);
            st[base + i * sm] = a;
        }
    }
    __syncthreads();
}

// ---------------- main: whole circuit per batch element in SMEM -------------
// SMEM floats: st[20000] | Up[12000] | BSb[1340] | Eg[1600]
#define SM_UP  20000
#define SM_BSB 32000
#define SM_EG  33340
#define SM_FLOATS 34940

__global__ void __launch_bounds__(NTHR, 1) k_main(const float* __restrict__ w_dense,
                                                  const float* __restrict__ b_dense,
                                                  float* __restrict__ out) {
    extern __shared__ float shf[];
    float2* st  = (float2*)shf;
    float*  Up  = shf + SM_UP;
    float2* BSb = (float2*)(shf + SM_BSB);
    float2* Eg  = (float2*)(shf + SM_EG);
    __shared__ float2 psi[40];
    __shared__ float redsh[96];

    int tid = threadIdx.x;
    int b = blockIdx.x;

    // ---- stage all tables once ----
    {
        const float4* src = (const float4*)g_CXp;
        float4* dst = (float4*)Up;
        for (int e = tid; e < 3000; e += NTHR) dst[e] = src[e];
    }
    for (int idx = tid; idx < 670; idx += NTHR) BSb[idx] = g_BSb[idx];
    for (int idx = tid; idx < 800; idx += NTHR) Eg[idx] = g_Elay[idx];
    if (tid < 40) psi[tid] = g_psi[b * 40 + tid];
    __syncthreads();

    // ---- init: outer product of encoded per-wire vectors ----
    for (int e = tid; e < 10000; e += NTHR) {
        int i0 = e / 1000; int r = e - i0 * 1000;
        int i1 = r / 100;  r -= i1 * 100;
        int i2 = r / 10;   int i3 = r - i2 * 10;
        st[e] = cmul(cmul(psi[i0], psi[10 + i1]), cmul(psi[20 + i2], psi[30 + i3]));
    }
    __syncthreads();

#pragma unroll 1
    for (int L = 0; L < 2; L++) {
        // ---- 6 CX gates (real, packed U), reference order ----
        pass_cx<1000, 100, 10, 1>(st, Up, tid);    // (0,1)
        pass_cx<1000, 10, 100, 1>(st, Up, tid);    // (0,2)
        pass_cx<1000, 1, 100, 10>(st, Up, tid);    // (0,3)
        pass_cx<100, 10, 1000, 1>(st, Up, tid);    // (1,2)
        pass_cx<100, 1, 1000, 10>(st, Up, tid);    // (1,3)
        pass_cx<10, 1, 1000, 100>(st, Up, tid);    // (2,3)

        // ---- 4 BS gates (photon-number blocks) ----
        pass_bs<1000, 100, 10, 1>(st, BSb, tid);   // (0,1)
        pass_bs<100, 10, 1000, 1>(st, BSb, tid);   // (1,2)
        pass_bs<10, 1, 1000, 100>(st, BSb, tid);   // (2,3)
        pass_bs<1, 1000, 100, 10>(st, BSb, tid);   // (3,0)

        // ---- 4 merged single-mode E = D@S gates ----
        pass_e(st, Eg + (L * 4 + 0) * 100, 1000, tid);
        pass_e(st, Eg + (L * 4 + 1) * 100, 100,  tid);
        pass_e(st, Eg + (L * 4 + 2) * 100, 10,   tid);
        pass_e(st, Eg + (L * 4 + 3) * 100, 1,    tid);
    }

    // ---- photon-number readout on modes 0..2, dense head ----
    float p0 = 0.f, p1 = 0.f, p2 = 0.f;
    for (int e = tid; e < 10000; e += NTHR) {
        float2 v = st[e];
        float pr = v.x * v.x + v.y * v.y;
        int i0 = e / 1000; int r = e - i0 * 1000;
        int i1 = r / 100;  r -= i1 * 100;
        int i2 = r / 10;
        p0 += pr * (float)i0;
        p1 += pr * (float)i1;
        p2 += pr * (float)i2;
    }
#pragma unroll
    for (int o = 16; o > 0; o >>= 1) {
        p0 += __shfl_down_sync(0xffffffffu, p0, o);
        p1 += __shfl_down_sync(0xffffffffu, p1, o);
        p2 += __shfl_down_sync(0xffffffffu, p2, o);
    }
    int wid = tid >> 5, lane = tid & 31;
    if (lane == 0) { redsh[wid] = p0; redsh[32 + wid] = p1; redsh[64 + wid] = p2; }
    __syncthreads();
    if (tid == 0) {
        float q0 = 0.f, q1 = 0.f, q2 = 0.f;
        for (int w = 0; w < 32; w++) { q0 += redsh[w]; q1 += redsh[32 + w]; q2 += redsh[64 + w]; }
        out[b] = q0 * w_dense[0] + q1 * w_dense[1] + q2 * w_dense[2] + b_dense[0];
    }
}

// ---------------- launch -----------------------------------------------------
extern "C" void kernel_launch(void* const* d_in, const int* in_sizes, int n_in,
                              void* d_out, int out_size) {
    const float* jets    = (const float*)d_in[0];
    const float* s_scale = (const float*)d_in[1];
    const float* dmag    = (const float*)d_in[2];
    const float* dph     = (const float*)d_in[3];
    const float* smag    = (const float*)d_in[4];
    const float* sph     = (const float*)d_in[5];
    const float* w_dense = (const float*)d_in[6];
    const float* b_dense = (const float*)d_in[7];
    float* out = (float*)d_out;

    const int smem_main = SM_FLOATS * 4;   // 139760 bytes
    const int smem_g = 10000 * 8;          // 80000 bytes
    cudaFuncSetAttribute(k_main,     cudaFuncAttributeMaxDynamicSharedMemorySize, smem_main);
    cudaFuncSetAttribute(k_g_taylor, cudaFuncAttributeMaxDynamicSharedMemorySize, smem_g);
    cudaFuncSetAttribute(k_g_square, cudaFuncAttributeMaxDynamicSharedMemorySize, smem_g);

    k_enc<<<NB * 4 + 8, 128>>>(jets, s_scale, dmag, dph, smag, sph);
    k_g_init<<<2, 512>>>();
    for (int j = 2; j <= 8; j++)
        k_g_taylor<<<40, 512, smem_g>>>(j, j & 1);
    for (int it = 0; it < 6; it++)
        k_g_square<<<40, 512, smem_g>>>(it & 1);
    k_pack<<<55, 256>>>();
    k_main<<<NB, NTHR, smem_main>>>(w_dense, b_dense, out);
}

// round 14
// speedup vs baseline: 2.9875x; 1.2964x over previous
#include <cuda_runtime.h>
#include <math.h>

#define NB   2048
#define NTHR 1024

// ---------------- global scratch -------------------------------------------
__device__ float2 g_psi[NB * 4 * 10];       // encoded per-wire vectors
__device__ float2 g_Elay[8 * 100];          // merged layer 10x10 complex gates (D@S)
__device__ __align__(16) float2 g_Xm[2][10000];   // scaled generators (CX, BS)
__device__ __align__(16) float2 g_Tp[2][2][10000];// Taylor term ping-pong
__device__ __align__(16) float2 g_Sp[2][2][10000];// partial sum ping-pong
__device__ __align__(16) float  g_CXp[12000];     // CX real, packed [k1][o][12]
__device__ float2 g_BSb[670];                     // BS photon-number blocks packed

// BS block tables
__constant__ int d_bsz[19] = {1,2,3,4,5,6,7,8,9,10,9,8,7,6,5,4,3,2,1};
__constant__ int d_off[19] = {0,1,5,14,30,55,91,140,204,285,385,466,530,579,615,640,656,665,669};
__constant__ int d_lo[19]  = {0,0,0,0,0,0,0,0,0,0,1,2,3,4,5,6,7,8,9};

// ---------------- complex helpers ------------------------------------------
__device__ __forceinline__ float2 cmul(float2 a, float2 b) {
    return make_float2(a.x * b.x - a.y * b.y, a.x * b.y + a.y * b.x);
}
__device__ __forceinline__ void cmacc(float2& acc, float2 a, float2 b) {
    acc.x = fmaf(a.x, b.x, fmaf(-a.y, b.y, acc.x));
    acc.y = fmaf(a.x, b.y, fmaf( a.y, b.x, acc.y));
}

// ---------------- 10x10 expm (block-cooperative, >=128 thr) -----------------
__device__ void expm10(float2* X, float2* S, float2* T, float2* T2, float* red, int t) {
    if (t < 10) {
        float s = 0.f;
        for (int j = 0; j < 10; j++) { float2 v = X[t * 10 + j]; s += fabsf(v.x) + fabsf(v.y); }
        red[t] = s;
    }
    __syncthreads();
    if (t == 0) {
        float m = 0.f;
        for (int i = 0; i < 10; i++) m = fmaxf(m, red[i]);
        int s = 0;
        while (m > 0.5f && s < 40) { m *= 0.5f; s++; }
        red[10] = (float)s;
    }
    __syncthreads();
    int s = (int)red[10];
    float sc = ldexpf(1.f, -s);
    if (t < 100) {
        X[t].x *= sc; X[t].y *= sc;
        T[t] = X[t];
        float2 v = X[t];
        if (t % 11 == 0) v.x += 1.f;
        S[t] = v;
    }
    __syncthreads();
    for (int j = 2; j <= 13; j++) {
        float inv = 1.f / (float)j;
        if (t < 100) {
            int i = t / 10, c = t % 10;
            float2 acc = make_float2(0.f, 0.f);
#pragma unroll
            for (int k = 0; k < 10; k++) cmacc(acc, T[i * 10 + k], X[k * 10 + c]);
            T2[t] = make_float2(acc.x * inv, acc.y * inv);
        }
        __syncthreads();
        if (t < 100) { T[t] = T2[t]; S[t].x += T2[t].x; S[t].y += T2[t].y; }
        __syncthreads();
    }
    for (int it = 0; it < s; it++) {
        if (t < 100) {
            int i = t / 10, c = t % 10;
            float2 acc = make_float2(0.f, 0.f);
#pragma unroll
            for (int k = 0; k < 10; k++) cmacc(acc, S[i * 10 + k], S[k * 10 + c]);
            T2[t] = acc;
        }
        __syncthreads();
        if (t < 100) S[t] = T2[t];
        __syncthreads();
    }
}

// ---------------- prep: encoding vectors + layer 10x10 gates ----------------
__global__ void k_enc(const float* __restrict__ jets, const float* __restrict__ s_scale,
                      const float* __restrict__ dmag, const float* __restrict__ dph,
                      const float* __restrict__ smag, const float* __restrict__ sph) {
    __shared__ float2 B0[100], B1[100], B2[100], B3[100], B4[100];
    __shared__ float red[16];
    int t = threadIdx.x;
    int id = blockIdx.x;

    float r_s, p_s, r_d, p_d;
    if (id < NB * 4) {
        const float* j3 = jets + id * 3;
        float eta = j3[0], ph = j3[1], pt = j3[2];
        float sc = 10.f / (1.f + expf(-s_scale[0])) + 0.01f;
        r_s = eta;      p_s = pt * ph * 0.5f;
        r_d = sc * pt;  p_d = eta;
    } else {
        int lw = id - NB * 4;
        r_s = smag[lw]; p_s = sph[lw];
        r_d = dmag[lw]; p_d = dph[lw];
    }

    float2 z = make_float2(r_s * cosf(p_s), r_s * sinf(p_s));
    if (t < 100) {
        int i = t / 10, j = t % 10;
        float2 g = make_float2(0.f, 0.f);
        if (j == i + 2) {
            float v = sqrtf((float)((i + 1) * (i + 2)));
            g.x = 0.5f * z.x * v;  g.y = -0.5f * z.y * v;
        } else if (i == j + 2) {
            float v = sqrtf((float)((j + 1) * (j + 2)));
            g.x = -0.5f * z.x * v; g.y = -0.5f * z.y * v;
        }
        B0[t] = g;
    }
    __syncthreads();
    expm10(B0, B1, B2, B3, red, t);
    __syncthreads();

    float2 al = make_float2(r_d * cosf(p_d), r_d * sinf(p_d));
    if (t < 100) {
        int i = t / 10, j = t % 10;
        float2 g = make_float2(0.f, 0.f);
        if (i == j + 1) {
            float v = sqrtf((float)(j + 1));
            g.x = al.x * v;  g.y = al.y * v;
        } else if (j == i + 1) {
            float v = sqrtf((float)(i + 1));
            g.x = -al.x * v; g.y = al.y * v;
        }
        B0[t] = g;
    }
    __syncthreads();
    expm10(B0, B4, B2, B3, red, t);
    __syncthreads();

    if (id < NB * 4) {
        if (t < 10) {
            float2 acc = make_float2(0.f, 0.f);
#pragma unroll
            for (int k = 0; k < 10; k++) cmacc(acc, B4[t * 10 + k], B1[k * 10 + 0]);
            g_psi[id * 10 + t] = acc;
        }
    } else {
        if (t < 100) {
            int i = t / 10, j = t % 10;
            float2 acc = make_float2(0.f, 0.f);
#pragma unroll
            for (int k = 0; k < 10; k++) cmacc(acc, B4[i * 10 + k], B1[k * 10 + j]);
            g_Elay[(id - NB * 4) * 100 + t] = acc;
        }
    }
}

// ---------------- prep pipeline: 100x100 expm via parallel launches ---------
// Fixed scaling 1/64 (scaled norms <=0.32) + Taylor terms 2..8 + 6 squarings.
__global__ void k_g_init() {
    int m = blockIdx.x;            // 0 = CX, 1 = BS
    int t = threadIdx.x;
    const float PIO4 = 0.7853981633974483f;
    const float SCF = 1.0f / 64.0f;
    for (int e = t; e < 10000; e += blockDim.x) {
        int o = e / 100, in = e % 100;
        int i = o / 10, j = o % 10, k = in / 10, l = in % 10;
        float2 g = make_float2(0.f, 0.f);
        if (m == 0) {
            float x1 = 0.f;
            if (k == i + 1) x1 = sqrtf((float)(i + 1));
            else if (i == k + 1) x1 = sqrtf((float)(k + 1));
            float y1 = 0.f;
            if (l == j + 1) y1 += sqrtf((float)(j + 1));
            if (j == l + 1) y1 -= sqrtf((float)(l + 1));
            g.x = -0.5f * x1 * y1;
        } else {
            float v = 0.f;
            if (k == i + 1 && j == l + 1) v += sqrtf((float)(i + 1)) * sqrtf((float)(l + 1));
            if (i == k + 1 && l == j + 1) v += sqrtf((float)(k + 1)) * sqrtf((float)(j + 1));
            g.y = PIO4 * v;
        }
        g.x *= SCF; g.y *= SCF;
        g_Xm[m][e] = g;
        g_Tp[0][m][e] = g;
        float2 s = g;
        if (o == in) s.x += 1.f;
        g_Sp[0][m][e] = s;
    }
}

__global__ void k_g_taylor(int jterm, int par) {
    extern __shared__ float2 Xs[];                // 10000
    int m = blockIdx.x / 20, rblk = blockIdx.x % 20;
    for (int e = threadIdx.x; e < 10000; e += blockDim.x) Xs[e] = g_Xm[m][e];
    __syncthreads();
    int t = threadIdx.x;
    if (t >= 500) return;
    int row = rblk * 5 + t / 100, col = t % 100;
    const float2* T = g_Tp[par][m];
    float inv = 1.f / (float)jterm;
    float2 acc = make_float2(0.f, 0.f);
    for (int k = 0; k < 100; k++) cmacc(acc, T[row * 100 + k], Xs[k * 100 + col]);
    acc.x *= inv; acc.y *= inv;
    g_Tp[1 - par][m][row * 100 + col] = acc;
    float2 s = g_Sp[0][m][row * 100 + col];
    s.x += acc.x; s.y += acc.y;
    g_Sp[0][m][row * 100 + col] = s;
}

__global__ void k_g_square(int par) {
    extern __shared__ float2 Ss[];                // 10000
    int m = blockIdx.x / 20, rblk = blockIdx.x % 20;
    for (int e = threadIdx.x; e < 10000; e += blockDim.x) Ss[e] = g_Sp[par][m][e];
    __syncthreads();
    int t = threadIdx.x;
    if (t >= 500) return;
    int row = rblk * 5 + t / 100, col = t % 100;
    float2 acc = make_float2(0.f, 0.f);
    for (int k = 0; k < 100; k++) cmacc(acc, Ss[row * 100 + k], Ss[k * 100 + col]);
    g_Sp[1 - par][m][row * 100 + col] = acc;
}

// ---------------- prep: pack CX real [k1][o][12] + BS blocks ----------------
__global__ void k_pack() {
    int t = blockIdx.x * blockDim.x + threadIdx.x;
    if (t < 12000) {
        int kk = t / 1200, rem = t % 1200;
        int o = rem / 12, ll = rem % 12;
        g_CXp[t] = (ll < 10) ? g_Sp[0][0][o * 100 + kk * 10 + ll].x : 0.f;
    } else if (t < 13900) {
        int e = t - 12000;
        int N = e / 100, rc = e % 100;
        int r = rc / 10, cc = rc % 10;
        int b = d_bsz[N], lo = d_lo[N];
        if (r < b && cc < b) {
            int i = lo + r,  j = N - i;
            int k = lo + cc, l = N - k;
            g_BSb[d_off[N] + r * b + cc] = g_Sp[0][1][(i * 10 + j) * 100 + (k * 10 + l)];
        }
    }
}

// ---------------- main kernel passes (1024 thr, ping-pong buffers) ----------
// Real two-mode CX gate: src -> dst, ONE barrier (no in-place hazard).
template<int S1, int S2, int SA, int SB>
__device__ __forceinline__ void pass_cx(const float2* src, float2* dst, const float* Up, int tid) {
    if (tid < 1000) {
        int rb = tid / 100;
        int sp = tid - rb * 100;
        int base = (sp / 10) * SA + (sp % 10) * SB;
        float2 acc[10];
#pragma unroll
        for (int q = 0; q < 10; q++) acc[q] = make_float2(0.f, 0.f);
#pragma unroll 1
        for (int kk = 0; kk < 10; kk++) {
            float2 xr[10];
            const float2* rowp = src + base + kk * S1;
#pragma unroll
            for (int ll = 0; ll < 10; ll++) xr[ll] = rowp[ll * S2];
            const float* Uk = Up + kk * 1200 + rb * 120;
#pragma unroll
            for (int q = 0; q < 10; q++) {
                const float* Ur = Uk + q * 12;
                float4 u0 = *(const float4*)Ur;
                float4 u1 = *(const float4*)(Ur + 4);
                float2 u2 = *(const float2*)(Ur + 8);
                float ax = acc[q].x, ay = acc[q].y;
                ax = fmaf(u0.x, xr[0].x, ax); ay = fmaf(u0.x, xr[0].y, ay);
                ax = fmaf(u0.y, xr[1].x, ax); ay = fmaf(u0.y, xr[1].y, ay);
                ax = fmaf(u0.z, xr[2].x, ax); ay = fmaf(u0.z, xr[2].y, ay);
                ax = fmaf(u0.w, xr[3].x, ax); ay = fmaf(u0.w, xr[3].y, ay);
                ax = fmaf(u1.x, xr[4].x, ax); ay = fmaf(u1.x, xr[4].y, ay);
                ax = fmaf(u1.y, xr[5].x, ax); ay = fmaf(u1.y, xr[5].y, ay);
                ax = fmaf(u1.z, xr[6].x, ax); ay = fmaf(u1.z, xr[6].y, ay);
                ax = fmaf(u1.w, xr[7].x, ax); ay = fmaf(u1.w, xr[7].y, ay);
                ax = fmaf(u2.x, xr[8].x, ax); ay = fmaf(u2.x, xr[8].y, ay);
                ax = fmaf(u2.y, xr[9].x, ax); ay = fmaf(u2.y, xr[9].y, ay);
                acc[q].x = ax; acc[q].y = ay;
            }
        }
#pragma unroll
        for (int q = 0; q < 10; q++)
            dst[base + rb * S1 + q * S2] = acc[q];
    }
    __syncthreads();
}

// BS photon-number-block pass: src -> dst, one barrier.
template<int SI, int SJ, int SA, int SB>
__device__ __forceinline__ void pass_bs(const float2* src, float2* dst, const float2* BSb, int tid) {
    for (int it = tid; it < 1900; it += NTHR) {
        int N = it / 100; int sp = it - N * 100;
        int b = d_bsz[N], lo = d_lo[N], of = d_off[N];
        int spa = sp / 10;
        int base = spa * SA + (sp - spa * 10) * SB;
        int ilo = base + lo * SI + (N - lo) * SJ;
        const int step = SI - SJ;
        float2 in[10];
        for (int c = 0; c < b; c++) in[c] = src[ilo + c * step];
        const float2* Bb = BSb + of;
        for (int r = 0; r < b; r++) {
            float2 acc = make_float2(0.f, 0.f);
            const float2* Br = Bb + r * b;
            for (int c = 0; c < b; c++) cmacc(acc, Br[c], in[c]);
            dst[ilo + r * step] = acc;
        }
    }
    __syncthreads();
}

// Complex single-mode gate: src -> dst, one barrier.
__device__ __forceinline__ void pass_e(const float2* src, float2* dst, const float2* E, int sm, int tid) {
    if (tid < 1000) {
        int base = (tid / sm) * (sm * 10) + (tid % sm);
        float2 in[10];
#pragma unroll
        for (int k = 0; k < 10; k++) in[k] = src[base + k * sm];
#pragma unroll
        for (int i = 0; i < 10; i++) {
            float2 a = make_float2(0.f, 0.f);
#pragma unroll
            for (int k = 0; k < 10; k++) cmacc(a, E[i * 10 + k], in[k]);
            dst[base + i * sm] = a;
        }
    }
    __syncthreads();
}

// Fused final E pass (mode 3, contiguous fibers) + photon accumulation.
// Outputs are never stored; pr contributions accumulate in registers.
__device__ __forceinline__ void pass_e_read(const float2* src, const float2* E, int tid,
                                            float& p0, float& p1, float& p2) {
    if (tid < 1000) {
        int base = tid * 10;
        float2 in[10];
#pragma unroll
        for (int k = 0; k < 10; k++) in[k] = src[base + k];
        float fi0 = (float)(tid / 100);
        float fi1 = (float)((tid / 10) % 10);
        float fi2 = (float)(tid % 10);
#pragma unroll
        for (int i = 0; i < 10; i++) {
            float2 a = make_float2(0.f, 0.f);
#pragma unroll
            for (int k = 0; k < 10; k++) cmacc(a, E[i * 10 + k], in[k]);
            float pr = a.x * a.x + a.y * a.y;
            p0 = fmaf(pr, fi0, p0);
            p1 = fmaf(pr, fi1, p1);
            p2 = fmaf(pr, fi2, p2);
        }
    }
}

// ---------------- main: whole circuit per batch element in SMEM -------------
// SMEM floats: st[20000] | st2[20000] | Up[12000] | BSb[1340] | Eg[1600]
#define SM_ST2 20000
#define SM_UP  40000
#define SM_BSB 52000
#define SM_EG  53340
#define SM_FLOATS 54940

__global__ void __launch_bounds__(NTHR, 1) k_main(const float* __restrict__ w_dense,
                                                  const float* __restrict__ b_dense,
                                                  float* __restrict__ out) {
    extern __shared__ float shf[];
    float2* stA = (float2*)shf;
    float2* stB = (float2*)(shf + SM_ST2);
    float*  Up  = shf + SM_UP;
    float2* BSb = (float2*)(shf + SM_BSB);
    float2* Eg  = (float2*)(shf + SM_EG);
    __shared__ float2 psi[40];
    __shared__ float redsh[96];

    int tid = threadIdx.x;
    int b = blockIdx.x;

    // ---- stage all tables once ----
    {
        const float4* src = (const float4*)g_CXp;
        float4* dst = (float4*)Up;
        for (int e = tid; e < 3000; e += NTHR) dst[e] = src[e];
    }
    for (int idx = tid; idx < 670; idx += NTHR) BSb[idx] = g_BSb[idx];
    for (int idx = tid; idx < 800; idx += NTHR) Eg[idx] = g_Elay[idx];
    if (tid < 40) psi[tid] = g_psi[b * 40 + tid];
    __syncthreads();

    // ---- init: outer product of encoded per-wire vectors (into stA) ----
    for (int e = tid; e < 10000; e += NTHR) {
        int i0 = e / 1000; int r = e - i0 * 1000;
        int i1 = r / 100;  r -= i1 * 100;
        int i2 = r / 10;   int i3 = r - i2 * 10;
        stA[e] = cmul(cmul(psi[i0], psi[10 + i1]), cmul(psi[20 + i2], psi[30 + i3]));
    }
    __syncthreads();

    float2* cur = stA;
    float2* oth = stB;
#define PSWAP { float2* tmp_ = cur; cur = oth; oth = tmp_; }

#pragma unroll 1
    for (int L = 0; L < 2; L++) {
        // ---- 6 CX gates (real, packed U), reference order ----
        pass_cx<1000, 100, 10, 1>(cur, oth, Up, tid); PSWAP;   // (0,1)
        pass_cx<1000, 10, 100, 1>(cur, oth, Up, tid); PSWAP;   // (0,2)
        pass_cx<1000, 1, 100, 10>(cur, oth, Up, tid); PSWAP;   // (0,3)
        pass_cx<100, 10, 1000, 1>(cur, oth, Up, tid); PSWAP;   // (1,2)
        pass_cx<100, 1, 1000, 10>(cur, oth, Up, tid); PSWAP;   // (1,3)
        pass_cx<10, 1, 1000, 100>(cur, oth, Up, tid); PSWAP;   // (2,3)

        // ---- 4 BS gates (photon-number blocks) ----
        pass_bs<1000, 100, 10, 1>(cur, oth, BSb, tid); PSWAP;  // (0,1)
        pass_bs<100, 10, 1000, 1>(cur, oth, BSb, tid); PSWAP;  // (1,2)
        pass_bs<10, 1, 1000, 100>(cur, oth, BSb, tid); PSWAP;  // (2,3)
        pass_bs<1, 1000, 100, 10>(cur, oth, BSb, tid); PSWAP;  // (3,0)

        // ---- merged single-mode E = D@S gates ----
        pass_e(cur, oth, Eg + (L * 4 + 0) * 100, 1000, tid); PSWAP;
        pass_e(cur, oth, Eg + (L * 4 + 1) * 100, 100,  tid); PSWAP;
        pass_e(cur, oth, Eg + (L * 4 + 2) * 100, 10,   tid); PSWAP;
        if (L == 0) { pass_e(cur, oth, Eg + 300, 1, tid); PSWAP; }
    }

    // ---- fused final E gate (L=1, mode 3) + photon-number readout ----
    float p0 = 0.f, p1 = 0.f, p2 = 0.f;
    pass_e_read(cur, Eg + 700, tid, p0, p1, p2);
#pragma unroll
    for (int o = 16; o > 0; o >>= 1) {
        p0 += __shfl_down_sync(0xffffffffu, p0, o);
        p1 += __shfl_down_sync(0xffffffffu, p1, o);
        p2 += __shfl_down_sync(0xffffffffu, p2, o);
    }
    int wid = tid >> 5, lane = tid & 31;
    if (lane == 0) { redsh[wid] = p0; redsh[32 + wid] = p1; redsh[64 + wid] = p2; }
    __syncthreads();
    if (tid == 0) {
        float q0 = 0.f, q1 = 0.f, q2 = 0.f;
        for (int w = 0; w < 32; w++) { q0 += redsh[w]; q1 += redsh[32 + w]; q2 += redsh[64 + w]; }
        out[b] = q0 * w_dense[0] + q1 * w_dense[1] + q2 * w_dense[2] + b_dense[0];
    }
}

// ---------------- launch -----------------------------------------------------
extern "C" void kernel_launch(void* const* d_in, const int* in_sizes, int n_in,
                              void* d_out, int out_size) {
    const float* jets    = (const float*)d_in[0];
    const float* s_scale = (const float*)d_in[1];
    const float* dmag    = (const float*)d_in[2];
    const float* dph     = (const float*)d_in[3];
    const float* smag    = (const float*)d_in[4];
    const float* sph     = (const float*)d_in[5];
    const float* w_dense = (const float*)d_in[6];
    const float* b_dense = (const float*)d_in[7];
    float* out = (float*)d_out;

    const int smem_main = SM_FLOATS * 4;   // 219760 bytes (opt-in < 227KB)
    const int smem_g = 10000 * 8;          // 80000 bytes
    cudaFuncSetAttribute(k_main,     cudaFuncAttributeMaxDynamicSharedMemorySize, smem_main);
    cudaFuncSetAttribute(k_g_taylor, cudaFuncAttributeMaxDynamicSharedMemorySize, smem_g);
    cudaFuncSetAttribute(k_g_square, cudaFuncAttributeMaxDynamicSharedMemorySize, smem_g);

    k_enc<<<NB * 4 + 8, 128>>>(jets, s_scale, dmag, dph, smag, sph);
    k_g_init<<<2, 512>>>();
    for (int j = 2; j <= 8; j++)
        k_g_taylor<<<40, 512, smem_g>>>(j, j & 1);
    for (int it = 0; it < 6; it++)
        k_g_square<<<40, 512, smem_g>>>(it & 1);
    k_pack<<<55, 256>>>();
    k_main<<<NB, NTHR, smem_main>>>(w_dense, b_dense, out);
}

// round 15
// speedup vs baseline: 4.0250x; 1.3473x over previous
#include <cuda_runtime.h>
#include <math.h>

#define NB   2048
#define NTHR 1024

// ---------------- global scratch -------------------------------------------
__device__ float2 g_psi[NB * 4 * 10];       // encoded per-wire vectors
__device__ float2 g_Elay[8 * 100];          // merged layer 10x10 complex gates (D@S)
__device__ __align__(16) float2 g_Xm[2][10000];   // scaled generators (CX, BS)
__device__ __align__(16) float2 g_Tp[2][2][10000];// Taylor term ping-pong
__device__ __align__(16) float2 g_Sp[2][2][10000];// partial sum ping-pong
__device__ __align__(16) float  g_CXq[8000];      // CX parity-packed [kk][rb][i][8]
__device__ float2 g_BSb[670];                     // BS photon-number blocks packed

// BS block tables
__constant__ int d_bsz[19] = {1,2,3,4,5,6,7,8,9,10,9,8,7,6,5,4,3,2,1};
__constant__ int d_off[19] = {0,1,5,14,30,55,91,140,204,285,385,466,530,579,615,640,656,665,669};
__constant__ int d_lo[19]  = {0,0,0,0,0,0,0,0,0,0,1,2,3,4,5,6,7,8,9};

// ---------------- complex helpers ------------------------------------------
__device__ __forceinline__ float2 cmul(float2 a, float2 b) {
    return make_float2(a.x * b.x - a.y * b.y, a.x * b.y + a.y * b.x);
}
__device__ __forceinline__ void cmacc(float2& acc, float2 a, float2 b) {
    acc.x = fmaf(a.x, b.x, fmaf(-a.y, b.y, acc.x));
    acc.y = fmaf(a.x, b.y, fmaf( a.y, b.x, acc.y));
}

// ---------------- 10x10 expm (block-cooperative, >=128 thr) -----------------
__device__ void expm10(float2* X, float2* S, float2* T, float2* T2, float* red, int t) {
    if (t < 10) {
        float s = 0.f;
        for (int j = 0; j < 10; j++) { float2 v = X[t * 10 + j]; s += fabsf(v.x) + fabsf(v.y); }
        red[t] = s;
    }
    __syncthreads();
    if (t == 0) {
        float m = 0.f;
        for (int i = 0; i < 10; i++) m = fmaxf(m, red[i]);
        int s = 0;
        while (m > 0.5f && s < 40) { m *= 0.5f; s++; }
        red[10] = (float)s;
    }
    __syncthreads();
    int s = (int)red[10];
    float sc = ldexpf(1.f, -s);
    if (t < 100) {
        X[t].x *= sc; X[t].y *= sc;
        T[t] = X[t];
        float2 v = X[t];
        if (t % 11 == 0) v.x += 1.f;
        S[t] = v;
    }
    __syncthreads();
    for (int j = 2; j <= 13; j++) {
        float inv = 1.f / (float)j;
        if (t < 100) {
            int i = t / 10, c = t % 10;
            float2 acc = make_float2(0.f, 0.f);
#pragma unroll
            for (int k = 0; k < 10; k++) cmacc(acc, T[i * 10 + k], X[k * 10 + c]);
            T2[t] = make_float2(acc.x * inv, acc.y * inv);
        }
        __syncthreads();
        if (t < 100) { T[t] = T2[t]; S[t].x += T2[t].x; S[t].y += T2[t].y; }
        __syncthreads();
    }
    for (int it = 0; it < s; it++) {
        if (t < 100) {
            int i = t / 10, c = t % 10;
            float2 acc = make_float2(0.f, 0.f);
#pragma unroll
            for (int k = 0; k < 10; k++) cmacc(acc, S[i * 10 + k], S[k * 10 + c]);
            T2[t] = acc;
        }
        __syncthreads();
        if (t < 100) S[t] = T2[t];
        __syncthreads();
    }
}

// ---------------- prep: encoding vectors + layer 10x10 gates ----------------
__global__ void k_enc(const float* __restrict__ jets, const float* __restrict__ s_scale,
                      const float* __restrict__ dmag, const float* __restrict__ dph,
                      const float* __restrict__ smag, const float* __restrict__ sph) {
    __shared__ float2 B0[100], B1[100], B2[100], B3[100], B4[100];
    __shared__ float red[16];
    int t = threadIdx.x;
    int id = blockIdx.x;

    float r_s, p_s, r_d, p_d;
    if (id < NB * 4) {
        const float* j3 = jets + id * 3;
        float eta = j3[0], ph = j3[1], pt = j3[2];
        float sc = 10.f / (1.f + expf(-s_scale[0])) + 0.01f;
        r_s = eta;      p_s = pt * ph * 0.5f;
        r_d = sc * pt;  p_d = eta;
    } else {
        int lw = id - NB * 4;
        r_s = smag[lw]; p_s = sph[lw];
        r_d = dmag[lw]; p_d = dph[lw];
    }

    float2 z = make_float2(r_s * cosf(p_s), r_s * sinf(p_s));
    if (t < 100) {
        int i = t / 10, j = t % 10;
        float2 g = make_float2(0.f, 0.f);
        if (j == i + 2) {
            float v = sqrtf((float)((i + 1) * (i + 2)));
            g.x = 0.5f * z.x * v;  g.y = -0.5f * z.y * v;
        } else if (i == j + 2) {
            float v = sqrtf((float)((j + 1) * (j + 2)));
            g.x = -0.5f * z.x * v; g.y = -0.5f * z.y * v;
        }
        B0[t] = g;
    }
    __syncthreads();
    expm10(B0, B1, B2, B3, red, t);
    __syncthreads();

    float2 al = make_float2(r_d * cosf(p_d), r_d * sinf(p_d));
    if (t < 100) {
        int i = t / 10, j = t % 10;
        float2 g = make_float2(0.f, 0.f);
        if (i == j + 1) {
            float v = sqrtf((float)(j + 1));
            g.x = al.x * v;  g.y = al.y * v;
        } else if (j == i + 1) {
            float v = sqrtf((float)(i + 1));
            g.x = -al.x * v; g.y = al.y * v;
        }
        B0[t] = g;
    }
    __syncthreads();
    expm10(B0, B4, B2, B3, red, t);
    __syncthreads();

    if (id < NB * 4) {
        if (t < 10) {
            float2 acc = make_float2(0.f, 0.f);
#pragma unroll
            for (int k = 0; k < 10; k++) cmacc(acc, B4[t * 10 + k], B1[k * 10 + 0]);
            g_psi[id * 10 + t] = acc;
        }
    } else {
        if (t < 100) {
            int i = t / 10, j = t % 10;
            float2 acc = make_float2(0.f, 0.f);
#pragma unroll
            for (int k = 0; k < 10; k++) cmacc(acc, B4[i * 10 + k], B1[k * 10 + j]);
            g_Elay[(id - NB * 4) * 100 + t] = acc;
        }
    }
}

// ---------------- prep pipeline: 100x100 expm via parallel launches ---------
// Fixed scaling 1/64 (scaled norms <=0.32) + Taylor terms 2..8 + 6 squarings.
__global__ void k_g_init() {
    int m = blockIdx.x;            // 0 = CX, 1 = BS
    int t = threadIdx.x;
    const float PIO4 = 0.7853981633974483f;
    const float SCF = 1.0f / 64.0f;
    for (int e = t; e < 10000; e += blockDim.x) {
        int o = e / 100, in = e % 100;
        int i = o / 10, j = o % 10, k = in / 10, l = in % 10;
        float2 g = make_float2(0.f, 0.f);
        if (m == 0) {
            float x1 = 0.f;
            if (k == i + 1) x1 = sqrtf((float)(i + 1));
            else if (i == k + 1) x1 = sqrtf((float)(k + 1));
            float y1 = 0.f;
            if (l == j + 1) y1 += sqrtf((float)(j + 1));
            if (j == l + 1) y1 -= sqrtf((float)(l + 1));
            g.x = -0.5f * x1 * y1;
        } else {
            float v = 0.f;
            if (k == i + 1 && j == l + 1) v += sqrtf((float)(i + 1)) * sqrtf((float)(l + 1));
            if (i == k + 1 && l == j + 1) v += sqrtf((float)(k + 1)) * sqrtf((float)(j + 1));
            g.y = PIO4 * v;
        }
        g.x *= SCF; g.y *= SCF;
        g_Xm[m][e] = g;
        g_Tp[0][m][e] = g;
        float2 s = g;
        if (o == in) s.x += 1.f;
        g_Sp[0][m][e] = s;
    }
}

__global__ void k_g_taylor(int jterm, int par) {
    extern __shared__ float2 Xs[];                // 10000
    int m = blockIdx.x / 20, rblk = blockIdx.x % 20;
    for (int e = threadIdx.x; e < 10000; e += blockDim.x) Xs[e] = g_Xm[m][e];
    __syncthreads();
    int t = threadIdx.x;
    if (t >= 500) return;
    int row = rblk * 5 + t / 100, col = t % 100;
    const float2* T = g_Tp[par][m];
    float inv = 1.f / (float)jterm;
    float2 acc = make_float2(0.f, 0.f);
    for (int k = 0; k < 100; k++) cmacc(acc, T[row * 100 + k], Xs[k * 100 + col]);
    acc.x *= inv; acc.y *= inv;
    g_Tp[1 - par][m][row * 100 + col] = acc;
    float2 s = g_Sp[0][m][row * 100 + col];
    s.x += acc.x; s.y += acc.y;
    g_Sp[0][m][row * 100 + col] = s;
}

__global__ void k_g_square(int par) {
    extern __shared__ float2 Ss[];                // 10000
    int m = blockIdx.x / 20, rblk = blockIdx.x % 20;
    for (int e = threadIdx.x; e < 10000; e += blockDim.x) Ss[e] = g_Sp[par][m][e];
    __syncthreads();
    int t = threadIdx.x;
    if (t >= 500) return;
    int row = rblk * 5 + t / 100, col = t % 100;
    float2 acc = make_float2(0.f, 0.f);
    for (int k = 0; k < 100; k++) cmacc(acc, Ss[row * 100 + k], Ss[k * 100 + col]);
    g_Sp[1 - par][m][row * 100 + col] = acc;
}

// ---------------- prep: pack parity CX + BS blocks --------------------------
// g_CXq[((kk*10 + rb)*10 + i)*8 + lp], rb -> p=rb&1, g=rb>>1.
// output o = i*10 + j, j = 2g + (p^(i&1)); input = kk*10 + ll, ll = 2lp + (p^(kk&1)).
__global__ void k_pack() {
    int t = blockIdx.x * blockDim.x + threadIdx.x;
    if (t < 8000) {
        int s = t & 7;
        int rem = t >> 3;               // (kk*10 + rb)*10 + i
        int i = rem % 10;
        int kr = rem / 10;
        int rb = kr % 10, kk = kr / 10;
        float v = 0.f;
        if (s < 5) {
            int p = rb & 1, g = rb >> 1;
            int j = 2 * g + (p ^ (i & 1));
            int ll = 2 * s + (p ^ (kk & 1));
            v = g_Sp[0][0][(i * 10 + j) * 100 + kk * 10 + ll].x;
        }
        g_CXq[t] = v;
    } else if (t < 9900) {
        int e = t - 8000;
        int N = e / 100, rc = e % 100;
        int r = rc / 10, cc = rc % 10;
        int b = d_bsz[N], lo = d_lo[N];
        if (r < b && cc < b) {
            int i = lo + r,  j = N - i;
            int k = lo + cc, l = N - k;
            g_BSb[d_off[N] + r * b + cc] = g_Sp[0][1][(i * 10 + j) * 100 + (k * 10 + l)];
        }
    }
}

// ---------------- main kernel passes (1024 thr, ping-pong, parity CX) -------
// Parity-blocked real CX: each thread owns 10 outputs of one parity.
template<int S1, int S2, int SA, int SB>
__device__ __forceinline__ void pass_cx(const float2* src, float2* dst, const float* Uq, int tid) {
    if (tid < 1000) {
        int rb = tid / 100;
        int sp = tid - rb * 100;
        int base = (sp / 10) * SA + (sp % 10) * SB;
        int p = rb & 1, g = rb >> 1;
        float2 acc[10];
#pragma unroll
        for (int i = 0; i < 10; i++) acc[i] = make_float2(0.f, 0.f);
#pragma unroll 1
        for (int kk = 0; kk < 10; kk++) {
            int off = p ^ (kk & 1);
            const float2* rowp = src + base + kk * S1 + off * S2;
            float2 xs0 = rowp[0];
            float2 xs1 = rowp[2 * S2];
            float2 xs2 = rowp[4 * S2];
            float2 xs3 = rowp[6 * S2];
            float2 xs4 = rowp[8 * S2];
            const float* Uk = Uq + (kk * 10 + rb) * 80;
#pragma unroll
            for (int i = 0; i < 10; i++) {
                float4 u = *(const float4*)(Uk + i * 8);
                float u4 = Uk[i * 8 + 4];
                float ax = acc[i].x, ay = acc[i].y;
                ax = fmaf(u.x, xs0.x, ax); ay = fmaf(u.x, xs0.y, ay);
                ax = fmaf(u.y, xs1.x, ax); ay = fmaf(u.y, xs1.y, ay);
                ax = fmaf(u.z, xs2.x, ax); ay = fmaf(u.z, xs2.y, ay);
                ax = fmaf(u.w, xs3.x, ax); ay = fmaf(u.w, xs3.y, ay);
                ax = fmaf(u4,  xs4.x, ax); ay = fmaf(u4,  xs4.y, ay);
                acc[i].x = ax; acc[i].y = ay;
            }
        }
#pragma unroll
        for (int i = 0; i < 10; i++) {
            int j = 2 * g + (p ^ (i & 1));
            dst[base + i * S1 + j * S2] = acc[i];
        }
    }
    __syncthreads();
}

// BS photon-number-block pass: src -> dst, one barrier.
template<int SI, int SJ, int SA, int SB>
__device__ __forceinline__ void pass_bs(const float2* src, float2* dst, const float2* BSb, int tid) {
    for (int it = tid; it < 1900; it += NTHR) {
        int N = it / 100; int sp = it - N * 100;
        int b = d_bsz[N], lo = d_lo[N], of = d_off[N];
        int spa = sp / 10;
        int base = spa * SA + (sp - spa * 10) * SB;
        int ilo = base + lo * SI + (N - lo) * SJ;
        const int step = SI - SJ;
        float2 in[10];
        for (int c = 0; c < b; c++) in[c] = src[ilo + c * step];
        const float2* Bb = BSb + of;
        for (int r = 0; r < b; r++) {
            float2 acc = make_float2(0.f, 0.f);
            const float2* Br = Bb + r * b;
            for (int c = 0; c < b; c++) cmacc(acc, Br[c], in[c]);
            dst[ilo + r * step] = acc;
        }
    }
    __syncthreads();
}

// Complex single-mode gate: src -> dst, one barrier.
__device__ __forceinline__ void pass_e(const float2* src, float2* dst, const float2* E, int sm, int tid) {
    if (tid < 1000) {
        int base = (tid / sm) * (sm * 10) + (tid % sm);
        float2 in[10];
#pragma unroll
        for (int k = 0; k < 10; k++) in[k] = src[base + k * sm];
#pragma unroll
        for (int i = 0; i < 10; i++) {
            float2 a = make_float2(0.f, 0.f);
#pragma unroll
            for (int k = 0; k < 10; k++) cmacc(a, E[i * 10 + k], in[k]);
            dst[base + i * sm] = a;
        }
    }
    __syncthreads();
}

// Fused final E pass (mode 3, contiguous fibers) + photon accumulation.
__device__ __forceinline__ void pass_e_read(const float2* src, const float2* E, int tid,
                                            float& p0, float& p1, float& p2) {
    if (tid < 1000) {
        int base = tid * 10;
        float2 in[10];
#pragma unroll
        for (int k = 0; k < 10; k++) in[k] = src[base + k];
        float fi0 = (float)(tid / 100);
        float fi1 = (float)((tid / 10) % 10);
        float fi2 = (float)(tid % 10);
#pragma unroll
        for (int i = 0; i < 10; i++) {
            float2 a = make_float2(0.f, 0.f);
#pragma unroll
            for (int k = 0; k < 10; k++) cmacc(a, E[i * 10 + k], in[k]);
            float pr = a.x * a.x + a.y * a.y;
            p0 = fmaf(pr, fi0, p0);
            p1 = fmaf(pr, fi1, p1);
            p2 = fmaf(pr, fi2, p2);
        }
    }
}

// ---------------- main: whole circuit per batch element in SMEM -------------
// SMEM floats: st[20000] | st2[20000] | Uq[8000] | BSb[1340] | Eg[1600]
#define SM_ST2 20000
#define SM_UQ  40000
#define SM_BSB 48000
#define SM_EG  49340
#define SM_FLOATS 50940

__global__ void __launch_bounds__(NTHR, 1) k_main(const float* __restrict__ w_dense,
                                                  const float* __restrict__ b_dense,
                                                  float* __restrict__ out) {
    extern __shared__ float shf[];
    float2* stA = (float2*)shf;
    float2* stB = (float2*)(shf + SM_ST2);
    float*  Uq  = shf + SM_UQ;
    float2* BSb = (float2*)(shf + SM_BSB);
    float2* Eg  = (float2*)(shf + SM_EG);
    __shared__ float2 psi[40];
    __shared__ float redsh[96];

    int tid = threadIdx.x;
    int b = blockIdx.x;

    // ---- stage all tables once ----
    {
        const float4* src = (const float4*)g_CXq;
        float4* dst = (float4*)Uq;
        for (int e = tid; e < 2000; e += NTHR) dst[e] = src[e];
    }
    for (int idx = tid; idx < 670; idx += NTHR) BSb[idx] = g_BSb[idx];
    for (int idx = tid; idx < 800; idx += NTHR) Eg[idx] = g_Elay[idx];
    if (tid < 40) psi[tid] = g_psi[b * 40 + tid];
    __syncthreads();

    // ---- init: outer product of encoded per-wire vectors (into stA) ----
    for (int e = tid; e < 10000; e += NTHR) {
        int i0 = e / 1000; int r = e - i0 * 1000;
        int i1 = r / 100;  r -= i1 * 100;
        int i2 = r / 10;   int i3 = r - i2 * 10;
        stA[e] = cmul(cmul(psi[i0], psi[10 + i1]), cmul(psi[20 + i2], psi[30 + i3]));
    }
    __syncthreads();

    float2* cur = stA;
    float2* oth = stB;
#define PSWAP { float2* tmp_ = cur; cur = oth; oth = tmp_; }

#pragma unroll 1
    for (int L = 0; L < 2; L++) {
        // ---- 6 CX gates (parity-blocked real), reference order ----
        pass_cx<1000, 100, 10, 1>(cur, oth, Uq, tid); PSWAP;   // (0,1)
        pass_cx<1000, 10, 100, 1>(cur, oth, Uq, tid); PSWAP;   // (0,2)
        pass_cx<1000, 1, 100, 10>(cur, oth, Uq, tid); PSWAP;   // (0,3)
        pass_cx<100, 10, 1000, 1>(cur, oth, Uq, tid); PSWAP;   // (1,2)
        pass_cx<100, 1, 1000, 10>(cur, oth, Uq, tid); PSWAP;   // (1,3)
        pass_cx<10, 1, 1000, 100>(cur, oth, Uq, tid); PSWAP;   // (2,3)

        // ---- 4 BS gates (photon-number blocks) ----
        pass_bs<1000, 100, 10, 1>(cur, oth, BSb, tid); PSWAP;  // (0,1)
        pass_bs<100, 10, 1000, 1>(cur, oth, BSb, tid); PSWAP;  // (1,2)
        pass_bs<10, 1, 1000, 100>(cur, oth, BSb, tid); PSWAP;  // (2,3)
        pass_bs<1, 1000, 100, 10>(cur, oth, BSb, tid); PSWAP;  // (3,0)

        // ---- merged single-mode E = D@S gates ----
        pass_e(cur, oth, Eg + (L * 4 + 0) * 100, 1000, tid); PSWAP;
        pass_e(cur, oth, Eg + (L * 4 + 1) * 100, 100,  tid); PSWAP;
        pass_e(cur, oth, Eg + (L * 4 + 2) * 100, 10,   tid); PSWAP;
        if (L == 0) { pass_e(cur, oth, Eg + 300, 1, tid); PSWAP; }
    }

    // ---- fused final E gate (L=1, mode 3) + photon-number readout ----
    float p0 = 0.f, p1 = 0.f, p2 = 0.f;
    pass_e_read(cur, Eg + 700, tid, p0, p1, p2);
#pragma unroll
    for (int o = 16; o > 0; o >>= 1) {
        p0 += __shfl_down_sync(0xffffffffu, p0, o);
        p1 += __shfl_down_sync(0xffffffffu, p1, o);
        p2 += __shfl_down_sync(0xffffffffu, p2, o);
    }
    int wid = tid >> 5, lane = tid & 31;
    if (lane == 0) { redsh[wid] = p0; redsh[32 + wid] = p1; redsh[64 + wid] = p2; }
    __syncthreads();
    if (tid == 0) {
        float q0 = 0.f, q1 = 0.f, q2 = 0.f;
        for (int w = 0; w < 32; w++) { q0 += redsh[w]; q1 += redsh[32 + w]; q2 += redsh[64 + w]; }
        out[b] = q0 * w_dense[0] + q1 * w_dense[1] + q2 * w_dense[2] + b_dense[0];
    }
}

// ---------------- launch -----------------------------------------------------
extern "C" void kernel_launch(void* const* d_in, const int* in_sizes, int n_in,
                              void* d_out, int out_size) {
    const float* jets    = (const float*)d_in[0];
    const float* s_scale = (const float*)d_in[1];
    const float* dmag    = (const float*)d_in[2];
    const float* dph     = (const float*)d_in[3];
    const float* smag    = (const float*)d_in[4];
    const float* sph     = (const float*)d_in[5];
    const float* w_dense = (const float*)d_in[6];
    const float* b_dense = (const float*)d_in[7];
    float* out = (float*)d_out;

    const int smem_main = SM_FLOATS * 4;   // 203760 bytes (opt-in < 227KB)
    const int smem_g = 10000 * 8;          // 80000 bytes
    cudaFuncSetAttribute(k_main,     cudaFuncAttributeMaxDynamicSharedMemorySize, smem_main);
    cudaFuncSetAttribute(k_g_taylor, cudaFuncAttributeMaxDynamicSharedMemorySize, smem_g);
    cudaFuncSetAttribute(k_g_square, cudaFuncAttributeMaxDynamicSharedMemorySize, smem_g);

    k_enc<<<NB * 4 + 8, 128>>>(jets, s_scale, dmag, dph, smag, sph);
    k_g_init<<<2, 512>>>();
    for (int j = 2; j <= 8; j++)
        k_g_taylor<<<40, 512, smem_g>>>(j, j & 1);
    for (int it = 0; it < 6; it++)
        k_g_square<<<40, 512, smem_g>>>(it & 1);
    k_pack<<<39, 256>>>();
    k_main<<<NB, NTHR, smem_main>>>(w_dense, b_dense, out);
}